// round 1
// baseline (speedup 1.0000x reference)
#include <cuda_runtime.h>
#include <math.h>
#include <stdint.h>

// ---------------- problem constants ----------------
#define NN    100000          // USER + ITEM
#define UU    50000           // USER (== ITEM)
#define DD    64              // LATDIM
#define EMAX  3200000         // N_EDGES per matrix
#define LEAK  0.2f
#define RIS_ADJ_LAMBDA 0.2f
#define RIS_LAMBDA     0.5f

// ---------------- static scratch (no runtime alloc allowed) ----------------
__device__ float g_e0   [(size_t)NN*DD];
__device__ float g_Xtxt [(size_t)NN*DD];
__device__ float g_XimgI[(size_t)UU*DD];
__device__ float g_S1   [(size_t)NN*DD];
__device__ float g_S2   [(size_t)NN*DD];
__device__ float g_S3   [(size_t)NN*DD];
__device__ float g_T1   [(size_t)NN*DD];
__device__ float g_T2   [(size_t)NN*DD];
__device__ float g_modal[(size_t)NN*DD];
__device__ float g_total[(size_t)NN*DD];
__device__ float g_E    [(size_t)NN*DD];
__device__ float g_cur  [(size_t)NN*DD];
__device__ float g_scores[NN];
__device__ float g_red[2];
__device__ int   g_counts[3*NN];
__device__ int   g_rowptr[3*(NN+1)];
__device__ int   g_woff  [3*NN];
__device__ int2  g_colval[(size_t)3*EMAX];

// ---------------- CSR build ----------------
__global__ void k_count(const int* __restrict__ rows, int* __restrict__ cnt, int ne) {
    int i = blockIdx.x * blockDim.x + threadIdx.x;
    if (i < ne) atomicAdd(&cnt[rows[i]], 1);
}

// one block (1024 thr) per matrix: exclusive scan of counts -> rowptr & woff
__global__ void k_scan(const int* __restrict__ counts, int* __restrict__ rowptr,
                       int* __restrict__ woff) {
    const int m = blockIdx.x;
    const int* c  = counts + (size_t)m * NN;
    int* rp = rowptr + (size_t)m * (NN + 1);
    int* wo = woff   + (size_t)m * NN;
    __shared__ int warp_sums[32];
    __shared__ int s_base;
    const int tid = threadIdx.x, lane = tid & 31, wid = tid >> 5;
    if (tid == 0) s_base = 0;
    __syncthreads();
    for (int chunk = 0; chunk < NN; chunk += 1024) {
        int idx = chunk + tid;
        int v = (idx < NN) ? c[idx] : 0;
        int inc = v;
        #pragma unroll
        for (int o = 1; o < 32; o <<= 1) {
            int t = __shfl_up_sync(0xffffffffu, inc, o);
            if (lane >= o) inc += t;
        }
        if (lane == 31) warp_sums[wid] = inc;
        __syncthreads();
        if (wid == 0) {
            int s = warp_sums[lane];
            #pragma unroll
            for (int o = 1; o < 32; o <<= 1) {
                int t = __shfl_up_sync(0xffffffffu, s, o);
                if (lane >= o) s += t;
            }
            warp_sums[lane] = s;  // inclusive over warp sums
        }
        __syncthreads();
        int warp_off = (wid == 0) ? 0 : warp_sums[wid - 1];
        int exc = s_base + warp_off + inc - v;
        if (idx < NN) { rp[idx] = exc; wo[idx] = exc; }
        __syncthreads();
        if (tid == 0) s_base += warp_sums[31];
        __syncthreads();
    }
    if (threadIdx.x == 0) rp[NN] = s_base;
}

__global__ void k_scatter(const int* __restrict__ rows, const int* __restrict__ cols,
                          const float* __restrict__ vals, int* __restrict__ woff,
                          int2* __restrict__ colval, int ne) {
    int i = blockIdx.x * blockDim.x + threadIdx.x;
    if (i >= ne) return;
    int r = rows[i];
    int p = atomicAdd(&woff[r], 1);
    colval[p] = make_int2(cols[i], __float_as_int(vals[i]));
}

// ---------------- SpMM (CSR gather, warp per row), optional score epilogue ----
__global__ void k_spmm(const int* __restrict__ rowptr, const int2* __restrict__ colval,
                       const float* __restrict__ x, float* __restrict__ y,
                       const float* __restrict__ attw, float* __restrict__ scores) {
    int warp = (blockIdx.x * blockDim.x + threadIdx.x) >> 5;
    if (warp >= NN) return;
    const int lane = threadIdx.x & 31;
    const int s = rowptr[warp], e = rowptr[warp + 1];
    float2 acc = make_float2(0.f, 0.f);
    for (int base = s; base < e; base += 32) {
        int2 cv = (base + lane < e) ? colval[base + lane] : make_int2(0, 0);
        int cnt = min(32, e - base);
        for (int j = 0; j < cnt; j++) {
            int   c = __shfl_sync(0xffffffffu, cv.x, j);
            float v = __int_as_float(__shfl_sync(0xffffffffu, cv.y, j));
            float2 xv = *(const float2*)(x + (size_t)c * DD + lane * 2);
            acc.x = fmaf(v, xv.x, acc.x);
            acc.y = fmaf(v, xv.y, acc.y);
        }
    }
    *(float2*)(y + (size_t)warp * DD + lane * 2) = acc;
    if (attw) {
        float sc = acc.x * attw[lane * 2] + acc.y * attw[lane * 2 + 1];
        #pragma unroll
        for (int o = 16; o; o >>= 1) sc += __shfl_xor_sync(0xffffffffu, sc, o);
        if (lane == 0) scores[warp] = sc;
    }
}

// ---------------- fused GEMM (M x K @ K x 64 + bias) + row l2norm ------------
// block: 64 rows x 64 cols, 256 threads, 4x4 per thread
__global__ void k_gemm_norm(const float* __restrict__ A, const float* __restrict__ W,
                            const float* __restrict__ bias, float* __restrict__ dst,
                            int M, int K) {
    __shared__ float  As[64][17];
    __shared__ float4 Bs[16][16];
    const int tid = threadIdx.x;
    const int tx = tid & 15;   // col group (4 cols)
    const int ty = tid >> 4;   // row group (4 rows, strided 16)
    const int rowBase = blockIdx.x * 64;
    float acc[4][4];
    #pragma unroll
    for (int i = 0; i < 4; i++)
        #pragma unroll
        for (int j = 0; j < 4; j++) acc[i][j] = 0.f;

    for (int kc = 0; kc < K; kc += 16) {
        {   // load A chunk [64 x 16]
            int r  = tid >> 2;
            int k4 = (tid & 3) * 4;
            float4 av = make_float4(0.f, 0.f, 0.f, 0.f);
            int gr = rowBase + r;
            if (gr < M) av = *(const float4*)&A[(size_t)gr * K + kc + k4];
            As[r][k4 + 0] = av.x; As[r][k4 + 1] = av.y;
            As[r][k4 + 2] = av.z; As[r][k4 + 3] = av.w;
        }
        {   // load W chunk [16 x 64]
            int kk = tid >> 4;
            int c4 = tid & 15;
            Bs[kk][c4] = *(const float4*)&W[(size_t)(kc + kk) * DD + c4 * 4];
        }
        __syncthreads();
        #pragma unroll
        for (int kk = 0; kk < 16; kk++) {
            float a0 = As[ty][kk],      a1 = As[ty + 16][kk];
            float a2 = As[ty + 32][kk], a3 = As[ty + 48][kk];
            float4 b = Bs[kk][tx];
            acc[0][0] = fmaf(a0, b.x, acc[0][0]); acc[0][1] = fmaf(a0, b.y, acc[0][1]);
            acc[0][2] = fmaf(a0, b.z, acc[0][2]); acc[0][3] = fmaf(a0, b.w, acc[0][3]);
            acc[1][0] = fmaf(a1, b.x, acc[1][0]); acc[1][1] = fmaf(a1, b.y, acc[1][1]);
            acc[1][2] = fmaf(a1, b.z, acc[1][2]); acc[1][3] = fmaf(a1, b.w, acc[1][3]);
            acc[2][0] = fmaf(a2, b.x, acc[2][0]); acc[2][1] = fmaf(a2, b.y, acc[2][1]);
            acc[2][2] = fmaf(a2, b.z, acc[2][2]); acc[2][3] = fmaf(a2, b.w, acc[2][3]);
            acc[3][0] = fmaf(a3, b.x, acc[3][0]); acc[3][1] = fmaf(a3, b.y, acc[3][1]);
            acc[3][2] = fmaf(a3, b.z, acc[3][2]); acc[3][3] = fmaf(a3, b.w, acc[3][3]);
        }
        __syncthreads();
    }
    // bias + row l2norm + store
    float b0 = bias[tx * 4 + 0], b1 = bias[tx * 4 + 1];
    float b2 = bias[tx * 4 + 2], b3 = bias[tx * 4 + 3];
    #pragma unroll
    for (int i = 0; i < 4; i++) {
        float v0 = acc[i][0] + b0, v1 = acc[i][1] + b1;
        float v2 = acc[i][2] + b2, v3 = acc[i][3] + b3;
        float ss = v0 * v0 + v1 * v1 + v2 * v2 + v3 * v3;
        // reduce across the 16 tx-lanes sharing this row (xor 1,2,4,8 stays in group)
        #pragma unroll
        for (int o = 1; o < 16; o <<= 1) ss += __shfl_xor_sync(0xffffffffu, ss, o);
        float inv = 1.f / fmaxf(sqrtf(ss), 1e-12f);
        int gr = rowBase + ty + i * 16;
        if (gr < M) {
            float4 out = make_float4(v0 * inv, v1 * inv, v2 * inv, v3 * inv);
            *(float4*)&dst[(size_t)gr * DD + tx * 4] = out;
        }
    }
}

// ---------------- elementwise glue ----------------
__global__ void k_concat(const float* __restrict__ u, const float* __restrict__ it,
                         float* __restrict__ e0, float* __restrict__ Xtxt) {
    size_t idx = (size_t)blockIdx.x * blockDim.x + threadIdx.x;
    if (idx >= (size_t)NN * DD) return;
    int n = (int)(idx >> 6);
    if (n < UU) { float v = u[idx]; e0[idx] = v; Xtxt[idx] = v; }
    else        { e0[idx] = it[idx - (size_t)UU * DD]; }
}

__global__ void k_copy_u(const float* __restrict__ src, float* __restrict__ dst) {
    size_t idx = (size_t)blockIdx.x * blockDim.x + threadIdx.x;
    if (idx < (size_t)UU * DD) dst[idx] = src[idx];
}

__global__ void k_combine(const float* __restrict__ u, const float* __restrict__ XimgI,
                          const float* __restrict__ S1, const float* __restrict__ S2,
                          const float* __restrict__ S3, const float* __restrict__ T1,
                          const float* __restrict__ T2, const float* __restrict__ mw,
                          float* __restrict__ modal, float* __restrict__ total) {
    size_t idx = (size_t)blockIdx.x * blockDim.x + threadIdx.x;
    if (idx >= (size_t)NN * DD) return;
    int n = (int)(idx >> 6);
    float a = mw[0], b = mw[1];
    float mx = fmaxf(a, b);
    float ea = expf(a - mx), eb = expf(b - mx);
    float w0 = ea / (ea + eb), w1 = eb / (ea + eb);
    float xi = (n < UU) ? u[idx] : XimgI[idx - (size_t)UU * DD];
    float ei = xi + S2[idx] + RIS_ADJ_LAMBDA * S1[idx];
    float et = T1[idx] + T2[idx] + RIS_ADJ_LAMBDA * S3[idx];
    float m = w0 * ei + w1 * et;
    modal[idx] = m;
    total[idx] = m;
}

// global softmax reduce over scores: red = {max, sum(exp(x-max))}
__global__ void k_reduce(const float* __restrict__ scores, float* __restrict__ red) {
    __shared__ float sm[32];
    const int tid = threadIdx.x, lane = tid & 31, wid = tid >> 5;
    float mx = -3.4e38f;
    for (int i = tid; i < NN; i += 1024) mx = fmaxf(mx, scores[i]);
    #pragma unroll
    for (int o = 16; o; o >>= 1) mx = fmaxf(mx, __shfl_xor_sync(0xffffffffu, mx, o));
    if (lane == 0) sm[wid] = mx;
    __syncthreads();
    if (wid == 0) {
        float m = sm[lane];
        #pragma unroll
        for (int o = 16; o; o >>= 1) m = fmaxf(m, __shfl_xor_sync(0xffffffffu, m, o));
        if (lane == 0) sm[0] = m;
    }
    __syncthreads();
    mx = sm[0];
    __syncthreads();
    float s = 0.f;
    for (int i = tid; i < NN; i += 1024) s += expf(scores[i] - mx);
    #pragma unroll
    for (int o = 16; o; o >>= 1) s += __shfl_xor_sync(0xffffffffu, s, o);
    if (lane == 0) sm[wid] = s;
    __syncthreads();
    if (wid == 0) {
        float t = sm[lane];
        #pragma unroll
        for (int o = 16; o; o >>= 1) t += __shfl_xor_sync(0xffffffffu, t, o);
        if (lane == 0) { red[0] = mx; red[1] = t; }
    }
}

__global__ void k_apply(const float* __restrict__ e, const float* __restrict__ scores,
                        const float* __restrict__ red, float* __restrict__ cur,
                        float* __restrict__ total) {
    size_t idx = (size_t)blockIdx.x * blockDim.x + threadIdx.x;
    if (idx >= (size_t)NN * DD) return;
    int n = (int)(idx >> 6);
    float att = expf(scores[n] - red[0]) / red[1];
    float v = e[idx] * att;
    v = (v > 0.f) ? v : LEAK * v;
    cur[idx] = v;
    total[idx] += v;
}

// out = total + RIS_LAMBDA * l2norm(modal); warp per row
__global__ void k_final(const float* __restrict__ modal, const float* __restrict__ total,
                        float* __restrict__ out) {
    int row = (blockIdx.x * blockDim.x + threadIdx.x) >> 5;
    if (row >= NN) return;
    const int lane = threadIdx.x & 31;
    size_t off = (size_t)row * DD + lane * 2;
    float2 m = *(const float2*)(modal + off);
    float ss = m.x * m.x + m.y * m.y;
    #pragma unroll
    for (int o = 16; o; o >>= 1) ss += __shfl_xor_sync(0xffffffffu, ss, o);
    float inv = 1.f / fmaxf(sqrtf(ss), 1e-12f);
    float2 t = *(const float2*)(total + off);
    float2 o2 = make_float2(t.x + RIS_LAMBDA * m.x * inv,
                            t.y + RIS_LAMBDA * m.y * inv);
    *(float2*)(out + off) = o2;
}

// ---------------- host launch sequence ----------------
extern "C" void kernel_launch(void* const* d_in, const int* in_sizes, int n_in,
                              void* d_out, int out_size) {
    const int*   adj_rows = (const int*)d_in[0];
    const int*   adj_cols = (const int*)d_in[1];
    const float* adj_vals = (const float*)d_in[2];
    const int*   img_rows = (const int*)d_in[3];
    const int*   img_cols = (const int*)d_in[4];
    const float* img_vals = (const float*)d_in[5];
    const int*   txt_rows = (const int*)d_in[6];
    const int*   txt_cols = (const int*)d_in[7];
    const float* txt_vals = (const float*)d_in[8];
    const float* u_emb    = (const float*)d_in[9];
    const float* i_emb    = (const float*)d_in[10];
    const float* img_W    = (const float*)d_in[11];
    const float* img_b    = (const float*)d_in[12];
    const float* txt_W    = (const float*)d_in[13];
    const float* txt_b    = (const float*)d_in[14];
    const float* modal_w  = (const float*)d_in[15];
    const float* att_w    = (const float*)d_in[16];
    const float* image_embedding = (const float*)d_in[17];
    const float* text_embedding  = (const float*)d_in[18];

    const int Eadj = in_sizes[0], Eimg = in_sizes[3], Etxt = in_sizes[6];

    float *e0, *Xtxt, *XimgI, *S1, *S2, *S3, *T1, *T2, *modal, *total, *Ebuf, *cur;
    float *scores, *red;
    int *counts, *rowptr, *woff;
    int2 *colval;
    cudaGetSymbolAddress((void**)&e0,    g_e0);
    cudaGetSymbolAddress((void**)&Xtxt,  g_Xtxt);
    cudaGetSymbolAddress((void**)&XimgI, g_XimgI);
    cudaGetSymbolAddress((void**)&S1,    g_S1);
    cudaGetSymbolAddress((void**)&S2,    g_S2);
    cudaGetSymbolAddress((void**)&S3,    g_S3);
    cudaGetSymbolAddress((void**)&T1,    g_T1);
    cudaGetSymbolAddress((void**)&T2,    g_T2);
    cudaGetSymbolAddress((void**)&modal, g_modal);
    cudaGetSymbolAddress((void**)&total, g_total);
    cudaGetSymbolAddress((void**)&Ebuf,  g_E);
    cudaGetSymbolAddress((void**)&cur,   g_cur);
    cudaGetSymbolAddress((void**)&scores,g_scores);
    cudaGetSymbolAddress((void**)&red,   g_red);
    cudaGetSymbolAddress((void**)&counts,g_counts);
    cudaGetSymbolAddress((void**)&rowptr,g_rowptr);
    cudaGetSymbolAddress((void**)&woff,  g_woff);
    cudaGetSymbolAddress((void**)&colval,g_colval);

    const int TPB = 256;
    const int ew_blocks   = (NN * DD + TPB - 1) / TPB;       // 25000
    const int row_blocks  = (NN * 32 + TPB - 1) / TPB;       // 12500 (warp/row)

    // ---- CSR build for 3 matrices ----
    cudaMemsetAsync(counts, 0, 3 * NN * sizeof(int));
    k_count<<<(Eadj + TPB - 1) / TPB, TPB>>>(adj_rows, counts + 0 * NN, Eadj);
    k_count<<<(Eimg + TPB - 1) / TPB, TPB>>>(img_rows, counts + 1 * NN, Eimg);
    k_count<<<(Etxt + TPB - 1) / TPB, TPB>>>(txt_rows, counts + 2 * NN, Etxt);
    k_scan<<<3, 1024>>>(counts, rowptr, woff);
    k_scatter<<<(Eadj + TPB - 1) / TPB, TPB>>>(adj_rows, adj_cols, adj_vals,
                                               woff + 0 * NN, colval + (size_t)0 * EMAX, Eadj);
    k_scatter<<<(Eimg + TPB - 1) / TPB, TPB>>>(img_rows, img_cols, img_vals,
                                               woff + 1 * NN, colval + (size_t)1 * EMAX, Eimg);
    k_scatter<<<(Etxt + TPB - 1) / TPB, TPB>>>(txt_rows, txt_cols, txt_vals,
                                               woff + 2 * NN, colval + (size_t)2 * EMAX, Etxt);

    const int* rp_adj = rowptr + 0 * (NN + 1);
    const int* rp_img = rowptr + 1 * (NN + 1);
    const int* rp_txt = rowptr + 2 * (NN + 1);
    const int2* cv_adj = colval + (size_t)0 * EMAX;
    const int2* cv_img = colval + (size_t)1 * EMAX;
    const int2* cv_txt = colval + (size_t)2 * EMAX;

    // ---- dense projections + l2norm; e0 / Xtxt assembly ----
    k_concat<<<ew_blocks, TPB>>>(u_emb, i_emb, e0, Xtxt);
    k_gemm_norm<<<(UU + 63) / 64, 256>>>(image_embedding, img_W, img_b, XimgI, UU, 1024);
    k_gemm_norm<<<(UU + 63) / 64, 256>>>(text_embedding,  txt_W, txt_b,
                                         Xtxt + (size_t)UU * DD, UU, 384);

    // ---- modality SpMMs ----
    // S1 = spmm(img, e0); S2 = spmm(adj, e0)  [== embeds_image_ since concat reduces to e0]
    // S3 = spmm(txt, e0); T1 = spmm(adj, Xtxt)
    k_spmm<<<row_blocks, TPB>>>(rp_img, cv_img, e0,   S1, nullptr, nullptr);
    k_spmm<<<row_blocks, TPB>>>(rp_adj, cv_adj, e0,   S2, nullptr, nullptr);
    k_spmm<<<row_blocks, TPB>>>(rp_txt, cv_txt, e0,   S3, nullptr, nullptr);
    k_spmm<<<row_blocks, TPB>>>(rp_adj, cv_adj, Xtxt, T1, nullptr, nullptr);
    // Y = concat(T1[:USER], i_embeds): e0's item half already holds i_embeds
    k_copy_u<<<(UU * DD + TPB - 1) / TPB, TPB>>>(T1, e0);
    k_spmm<<<row_blocks, TPB>>>(rp_adj, cv_adj, e0, T2, nullptr, nullptr);

    // ---- modal combine ----
    k_combine<<<ew_blocks, TPB>>>(u_emb, XimgI, S1, S2, S3, T1, T2, modal_w, modal, total);

    // ---- GNN layer 1 ----
    k_spmm<<<row_blocks, TPB>>>(rp_adj, cv_adj, modal, Ebuf, att_w + 0, scores);
    k_reduce<<<1, 1024>>>(scores, red);
    k_apply<<<ew_blocks, TPB>>>(Ebuf, scores, red, cur, total);
    // ---- GNN layer 2 ----
    k_spmm<<<row_blocks, TPB>>>(rp_adj, cv_adj, cur, Ebuf, att_w + DD, scores);
    k_reduce<<<1, 1024>>>(scores, red);
    k_apply<<<ew_blocks, TPB>>>(Ebuf, scores, red, cur, total);

    // ---- final: out = total + 0.5 * l2norm(modal) ----
    k_final<<<row_blocks, TPB>>>(modal, total, (float*)d_out);
}

// round 2
// speedup vs baseline: 1.1195x; 1.1195x over previous
#include <cuda_runtime.h>
#include <math.h>
#include <stdint.h>

// ---------------- problem constants ----------------
#define NN    100000          // USER + ITEM
#define UU    50000           // USER (== ITEM)
#define DD    64              // LATDIM
#define EMAX  3200000         // N_EDGES per matrix
#define LEAK  0.2f
#define RIS_ADJ_LAMBDA 0.2f
#define RIS_LAMBDA     0.5f

#define CHUNK 2048
#define NB    ((NN + CHUNK - 1) / CHUNK)   // 49 blocks per matrix for the scan

// ---------------- static scratch (no runtime alloc allowed) ----------------
__device__ float g_e0   [(size_t)NN*DD];
__device__ float g_Xtxt [(size_t)NN*DD];
__device__ float g_XimgI[(size_t)UU*DD];
__device__ float g_S1   [(size_t)NN*DD];
__device__ float g_S2   [(size_t)NN*DD];
__device__ float g_S3   [(size_t)NN*DD];
__device__ float g_T1   [(size_t)NN*DD];
__device__ float g_T2   [(size_t)NN*DD];
__device__ float g_modal[(size_t)NN*DD];
__device__ float g_total[(size_t)NN*DD];
__device__ float g_E    [(size_t)NN*DD];
__device__ float g_cur  [(size_t)NN*DD];
__device__ float g_scores[NN];
__device__ float g_red[2];
__device__ int   g_counts[3*NN];
__device__ int   g_rowptr[3*(NN+1)];
__device__ int   g_woff  [3*NN];
__device__ int   g_bsums [3*NB];
__device__ int2  g_colval[(size_t)3*EMAX];

// ---------------- f32x2 helpers ----------------
__device__ __forceinline__ unsigned long long pack2(float x, float y) {
    unsigned long long r;
    asm("mov.b64 %0, {%1,%2};" : "=l"(r) : "f"(x), "f"(y));
    return r;
}
__device__ __forceinline__ unsigned long long dup2(float v) { return pack2(v, v); }
__device__ __forceinline__ void unpack2(unsigned long long u, float& x, float& y) {
    asm("mov.b64 {%0,%1}, %2;" : "=f"(x), "=f"(y) : "l"(u));
}
__device__ __forceinline__ void ffma2(unsigned long long& d,
                                      unsigned long long a, unsigned long long b) {
    asm("fma.rn.f32x2 %0, %1, %2, %0;" : "+l"(d) : "l"(a), "l"(b));
}

// ---------------- CSR build ----------------
__global__ void k_count3(const int* __restrict__ r0, const int* __restrict__ r1,
                         const int* __restrict__ r2, int* __restrict__ cnt,
                         int e0, int e1, int e2) {
    int i = blockIdx.x * blockDim.x + threadIdx.x;
    if (i < e0) atomicAdd(&cnt[0 * NN + r0[i]], 1);
    if (i < e1) atomicAdd(&cnt[1 * NN + r1[i]], 1);
    if (i < e2) atomicAdd(&cnt[2 * NN + r2[i]], 1);
}

// phase 1: per-block sums
__global__ void k_scan1(const int* __restrict__ counts, int* __restrict__ bsums) {
    const int m = blockIdx.x / NB, b = blockIdx.x % NB;
    const int* c = counts + (size_t)m * NN;
    const int tid = threadIdx.x, lane = tid & 31, wid = tid >> 5;
    int base = b * CHUNK + tid * 8;
    int s = 0;
    #pragma unroll
    for (int k = 0; k < 8; k++) {
        int idx = base + k;
        if (idx < NN) s += c[idx];
    }
    #pragma unroll
    for (int o = 16; o; o >>= 1) s += __shfl_xor_sync(0xffffffffu, s, o);
    __shared__ int ws[8];
    if (lane == 0) ws[wid] = s;
    __syncthreads();
    if (tid == 0) {
        int t = 0;
        #pragma unroll
        for (int w = 0; w < 8; w++) t += ws[w];
        bsums[m * NB + b] = t;
    }
}

// phase 2: exclusive scan of the 49 block sums per matrix (3 threads)
__global__ void k_scan2(int* __restrict__ bsums, int* __restrict__ rowptr) {
    int m = threadIdx.x;
    if (m >= 3) return;
    int* bs = bsums + m * NB;
    int v[NB];
    #pragma unroll
    for (int i = 0; i < NB; i++) v[i] = bs[i];
    int run = 0;
    #pragma unroll
    for (int i = 0; i < NB; i++) { int t = v[i]; bs[i] = run; run += t; }
    rowptr[(size_t)m * (NN + 1) + NN] = run;
}

// phase 3: rescan each chunk with the block offset, write rowptr + woff
__global__ void k_scan3(const int* __restrict__ counts, const int* __restrict__ bsums,
                        int* __restrict__ rowptr, int* __restrict__ woff) {
    const int m = blockIdx.x / NB, b = blockIdx.x % NB;
    const int* c = counts + (size_t)m * NN;
    int* rp = rowptr + (size_t)m * (NN + 1);
    int* wo = woff + (size_t)m * NN;
    const int tid = threadIdx.x, lane = tid & 31, wid = tid >> 5;
    int base = b * CHUNK + tid * 8;
    int v[8], pre[8];
    int s = 0;
    #pragma unroll
    for (int k = 0; k < 8; k++) {
        int idx = base + k;
        v[k] = (idx < NN) ? c[idx] : 0;
        s += v[k];
        pre[k] = s;               // inclusive local
    }
    int tsum = s;
    // warp inclusive scan of thread sums
    int inc = tsum;
    #pragma unroll
    for (int o = 1; o < 32; o <<= 1) {
        int t = __shfl_up_sync(0xffffffffu, inc, o);
        if (lane >= o) inc += t;
    }
    __shared__ int ws[8];
    if (lane == 31) ws[wid] = inc;
    __syncthreads();
    int woffsum = 0;
    #pragma unroll
    for (int w = 0; w < 8; w++) woffsum += (w < wid) ? ws[w] : 0;
    int excl = bsums[m * NB + b] + woffsum + inc - tsum;
    #pragma unroll
    for (int k = 0; k < 8; k++) {
        int idx = base + k;
        if (idx < NN) {
            int e = excl + pre[k] - v[k];
            rp[idx] = e;
            wo[idx] = e;
        }
    }
}

__global__ void k_scatter3(const int* __restrict__ ar, const int* __restrict__ ac,
                           const float* __restrict__ av,
                           const int* __restrict__ ir, const int* __restrict__ ic,
                           const float* __restrict__ iv,
                           const int* __restrict__ tr, const int* __restrict__ tc,
                           const float* __restrict__ tv,
                           int* __restrict__ woff, int2* __restrict__ colval,
                           int e0, int e1, int e2) {
    int i = blockIdx.x * blockDim.x + threadIdx.x;
    if (i < e0) {
        int p = atomicAdd(&woff[0 * NN + ar[i]], 1);
        colval[(size_t)0 * EMAX + p] = make_int2(ac[i], __float_as_int(av[i]));
    }
    if (i < e1) {
        int p = atomicAdd(&woff[1 * NN + ir[i]], 1);
        colval[(size_t)1 * EMAX + p] = make_int2(ic[i], __float_as_int(iv[i]));
    }
    if (i < e2) {
        int p = atomicAdd(&woff[2 * NN + tr[i]], 1);
        colval[(size_t)2 * EMAX + p] = make_int2(tc[i], __float_as_int(tv[i]));
    }
}

// ---------------- SpMM (CSR gather, warp per row), optional score epilogue ----
__global__ void k_spmm(const int* __restrict__ rowptr, const int2* __restrict__ colval,
                       const float* __restrict__ x, float* __restrict__ y,
                       const float* __restrict__ attw, float* __restrict__ scores) {
    int row = (blockIdx.x * blockDim.x + threadIdx.x) >> 5;
    if (row >= NN) return;
    const int lane = threadIdx.x & 31;
    const int s = rowptr[row], e = rowptr[row + 1];
    float2 acc = make_float2(0.f, 0.f);
    int base = s;
    for (; base + 32 <= e; base += 32) {
        int2 cv = colval[base + lane];
        #pragma unroll
        for (int j = 0; j < 32; j++) {
            int   c = __shfl_sync(0xffffffffu, cv.x, j);
            float v = __int_as_float(__shfl_sync(0xffffffffu, cv.y, j));
            float2 xv = *(const float2*)(x + (size_t)c * DD + lane * 2);
            acc.x = fmaf(v, xv.x, acc.x);
            acc.y = fmaf(v, xv.y, acc.y);
        }
    }
    int rem = e - base;
    if (rem > 0) {
        int2 cv = (lane < rem) ? colval[base + lane] : make_int2(0, 0);
        for (int j = 0; j < rem; j++) {
            int   c = __shfl_sync(0xffffffffu, cv.x, j);
            float v = __int_as_float(__shfl_sync(0xffffffffu, cv.y, j));
            float2 xv = *(const float2*)(x + (size_t)c * DD + lane * 2);
            acc.x = fmaf(v, xv.x, acc.x);
            acc.y = fmaf(v, xv.y, acc.y);
        }
    }
    *(float2*)(y + (size_t)row * DD + lane * 2) = acc;
    if (attw) {
        float sc = acc.x * attw[lane * 2] + acc.y * attw[lane * 2 + 1];
        #pragma unroll
        for (int o = 16; o; o >>= 1) sc += __shfl_xor_sync(0xffffffffu, sc, o);
        if (lane == 0) scores[row] = sc;
    }
}

// dual-input SpMM over the same matrix: y1 = A@x1, y2 = A@x2 (edge stream read once)
__global__ void k_spmm2(const int* __restrict__ rowptr, const int2* __restrict__ colval,
                        const float* __restrict__ x1, const float* __restrict__ x2,
                        float* __restrict__ y1, float* __restrict__ y2) {
    int row = (blockIdx.x * blockDim.x + threadIdx.x) >> 5;
    if (row >= NN) return;
    const int lane = threadIdx.x & 31;
    const int s = rowptr[row], e = rowptr[row + 1];
    float2 a1 = make_float2(0.f, 0.f), a2 = make_float2(0.f, 0.f);
    int base = s;
    for (; base + 32 <= e; base += 32) {
        int2 cv = colval[base + lane];
        #pragma unroll
        for (int j = 0; j < 32; j++) {
            int   c = __shfl_sync(0xffffffffu, cv.x, j);
            float v = __int_as_float(__shfl_sync(0xffffffffu, cv.y, j));
            size_t off = (size_t)c * DD + lane * 2;
            float2 p = *(const float2*)(x1 + off);
            float2 q = *(const float2*)(x2 + off);
            a1.x = fmaf(v, p.x, a1.x); a1.y = fmaf(v, p.y, a1.y);
            a2.x = fmaf(v, q.x, a2.x); a2.y = fmaf(v, q.y, a2.y);
        }
    }
    int rem = e - base;
    if (rem > 0) {
        int2 cv = (lane < rem) ? colval[base + lane] : make_int2(0, 0);
        for (int j = 0; j < rem; j++) {
            int   c = __shfl_sync(0xffffffffu, cv.x, j);
            float v = __int_as_float(__shfl_sync(0xffffffffu, cv.y, j));
            size_t off = (size_t)c * DD + lane * 2;
            float2 p = *(const float2*)(x1 + off);
            float2 q = *(const float2*)(x2 + off);
            a1.x = fmaf(v, p.x, a1.x); a1.y = fmaf(v, p.y, a1.y);
            a2.x = fmaf(v, q.x, a2.x); a2.y = fmaf(v, q.y, a2.y);
        }
    }
    size_t off = (size_t)row * DD + lane * 2;
    *(float2*)(y1 + off) = a1;
    *(float2*)(y2 + off) = a2;
}

// ---------------- fused GEMM (M x K @ K x 64 + bias) + row l2norm ------------
// FFMA2 (f32x2) version. block: 64 rows x 64 cols, 256 threads, 4x4 per thread.
__global__ void k_gemm_norm(const float* __restrict__ A, const float* __restrict__ W,
                            const float* __restrict__ bias, float* __restrict__ dst,
                            int M, int K) {
    __shared__ unsigned long long As[64][17];   // duplicated a-value per slot
    __shared__ unsigned long long Bs[16][34];   // 32 col-pairs + pad
    const int tid = threadIdx.x;
    const int tx = tid & 15;   // col group (4 cols = 2 pairs)
    const int ty = tid >> 4;   // row group (4 rows, strided 16)
    const int rowBase = blockIdx.x * 64;
    unsigned long long acc[4][2];
    #pragma unroll
    for (int i = 0; i < 4; i++) { acc[i][0] = 0ull; acc[i][1] = 0ull; }

    for (int kc = 0; kc < K; kc += 16) {
        {   // A chunk [64 x 16], store duplicated
            int r  = tid >> 2;
            int k4 = (tid & 3) * 4;
            float4 av = make_float4(0.f, 0.f, 0.f, 0.f);
            int gr = rowBase + r;
            if (gr < M) av = *(const float4*)&A[(size_t)gr * K + kc + k4];
            As[r][k4 + 0] = dup2(av.x); As[r][k4 + 1] = dup2(av.y);
            As[r][k4 + 2] = dup2(av.z); As[r][k4 + 3] = dup2(av.w);
        }
        {   // W chunk [16 x 64] as f32x2 pairs
            int kk = tid >> 4;
            int c4 = tid & 15;
            float4 w = *(const float4*)&W[(size_t)(kc + kk) * DD + c4 * 4];
            Bs[kk][2 * c4 + 0] = pack2(w.x, w.y);
            Bs[kk][2 * c4 + 1] = pack2(w.z, w.w);
        }
        __syncthreads();
        #pragma unroll
        for (int kk = 0; kk < 16; kk++) {
            unsigned long long a0 = As[ty][kk],      a1 = As[ty + 16][kk];
            unsigned long long a2 = As[ty + 32][kk], a3 = As[ty + 48][kk];
            longlong2 bb = *(const longlong2*)&Bs[kk][2 * tx];
            unsigned long long b0 = (unsigned long long)bb.x;
            unsigned long long b1 = (unsigned long long)bb.y;
            ffma2(acc[0][0], a0, b0); ffma2(acc[0][1], a0, b1);
            ffma2(acc[1][0], a1, b0); ffma2(acc[1][1], a1, b1);
            ffma2(acc[2][0], a2, b0); ffma2(acc[2][1], a2, b1);
            ffma2(acc[3][0], a3, b0); ffma2(acc[3][1], a3, b1);
        }
        __syncthreads();
    }
    // bias + row l2norm + store
    float b0 = bias[tx * 4 + 0], b1 = bias[tx * 4 + 1];
    float b2 = bias[tx * 4 + 2], b3 = bias[tx * 4 + 3];
    #pragma unroll
    for (int i = 0; i < 4; i++) {
        float v0, v1, v2, v3;
        unpack2(acc[i][0], v0, v1);
        unpack2(acc[i][1], v2, v3);
        v0 += b0; v1 += b1; v2 += b2; v3 += b3;
        float ss = v0 * v0 + v1 * v1 + v2 * v2 + v3 * v3;
        #pragma unroll
        for (int o = 1; o < 16; o <<= 1) ss += __shfl_xor_sync(0xffffffffu, ss, o);
        float inv = 1.f / fmaxf(sqrtf(ss), 1e-12f);
        int gr = rowBase + ty + i * 16;
        if (gr < M) {
            float4 out = make_float4(v0 * inv, v1 * inv, v2 * inv, v3 * inv);
            *(float4*)&dst[(size_t)gr * DD + tx * 4] = out;
        }
    }
}

// ---------------- elementwise glue ----------------
__global__ void k_concat(const float* __restrict__ u, const float* __restrict__ it,
                         float* __restrict__ e0, float* __restrict__ Xtxt) {
    size_t idx = (size_t)blockIdx.x * blockDim.x + threadIdx.x;
    if (idx >= (size_t)NN * DD) return;
    int n = (int)(idx >> 6);
    if (n < UU) { float v = u[idx]; e0[idx] = v; Xtxt[idx] = v; }
    else        { e0[idx] = it[idx - (size_t)UU * DD]; }
}

__global__ void k_copy_u(const float* __restrict__ src, float* __restrict__ dst) {
    size_t idx = (size_t)blockIdx.x * blockDim.x + threadIdx.x;
    if (idx < (size_t)UU * DD) dst[idx] = src[idx];
}

__global__ void k_combine(const float* __restrict__ u, const float* __restrict__ XimgI,
                          const float* __restrict__ S1, const float* __restrict__ S2,
                          const float* __restrict__ S3, const float* __restrict__ T1,
                          const float* __restrict__ T2, const float* __restrict__ mw,
                          float* __restrict__ modal, float* __restrict__ total) {
    size_t idx = (size_t)blockIdx.x * blockDim.x + threadIdx.x;
    if (idx >= (size_t)NN * DD) return;
    int n = (int)(idx >> 6);
    float a = mw[0], b = mw[1];
    float mx = fmaxf(a, b);
    float ea = expf(a - mx), eb = expf(b - mx);
    float w0 = ea / (ea + eb), w1 = eb / (ea + eb);
    float xi = (n < UU) ? u[idx] : XimgI[idx - (size_t)UU * DD];
    float ei = xi + S2[idx] + RIS_ADJ_LAMBDA * S1[idx];
    float et = T1[idx] + T2[idx] + RIS_ADJ_LAMBDA * S3[idx];
    float m = w0 * ei + w1 * et;
    modal[idx] = m;
    total[idx] = m;
}

// global softmax reduce over scores: red = {max, sum(exp(x-max))}
__global__ void k_reduce(const float* __restrict__ scores, float* __restrict__ red) {
    __shared__ float sm[32];
    const int tid = threadIdx.x, lane = tid & 31, wid = tid >> 5;
    float mx = -3.4e38f;
    for (int i = tid; i < NN; i += 1024) mx = fmaxf(mx, scores[i]);
    #pragma unroll
    for (int o = 16; o; o >>= 1) mx = fmaxf(mx, __shfl_xor_sync(0xffffffffu, mx, o));
    if (lane == 0) sm[wid] = mx;
    __syncthreads();
    if (wid == 0) {
        float m = sm[lane];
        #pragma unroll
        for (int o = 16; o; o >>= 1) m = fmaxf(m, __shfl_xor_sync(0xffffffffu, m, o));
        if (lane == 0) sm[0] = m;
    }
    __syncthreads();
    mx = sm[0];
    __syncthreads();
    float s = 0.f;
    for (int i = tid; i < NN; i += 1024) s += expf(scores[i] - mx);
    #pragma unroll
    for (int o = 16; o; o >>= 1) s += __shfl_xor_sync(0xffffffffu, s, o);
    if (lane == 0) sm[wid] = s;
    __syncthreads();
    if (wid == 0) {
        float t = sm[lane];
        #pragma unroll
        for (int o = 16; o; o >>= 1) t += __shfl_xor_sync(0xffffffffu, t, o);
        if (lane == 0) { red[0] = mx; red[1] = t; }
    }
}

__global__ void k_apply(const float* __restrict__ e, const float* __restrict__ scores,
                        const float* __restrict__ red, float* __restrict__ cur,
                        float* __restrict__ total) {
    size_t idx = (size_t)blockIdx.x * blockDim.x + threadIdx.x;
    if (idx >= (size_t)NN * DD) return;
    int n = (int)(idx >> 6);
    float att = expf(scores[n] - red[0]) / red[1];
    float v = e[idx] * att;
    v = (v > 0.f) ? v : LEAK * v;
    cur[idx] = v;
    total[idx] += v;
}

// out = total + RIS_LAMBDA * l2norm(modal); warp per row
__global__ void k_final(const float* __restrict__ modal, const float* __restrict__ total,
                        float* __restrict__ out) {
    int row = (blockIdx.x * blockDim.x + threadIdx.x) >> 5;
    if (row >= NN) return;
    const int lane = threadIdx.x & 31;
    size_t off = (size_t)row * DD + lane * 2;
    float2 m = *(const float2*)(modal + off);
    float ss = m.x * m.x + m.y * m.y;
    #pragma unroll
    for (int o = 16; o; o >>= 1) ss += __shfl_xor_sync(0xffffffffu, ss, o);
    float inv = 1.f / fmaxf(sqrtf(ss), 1e-12f);
    float2 t = *(const float2*)(total + off);
    float2 o2 = make_float2(t.x + RIS_LAMBDA * m.x * inv,
                            t.y + RIS_LAMBDA * m.y * inv);
    *(float2*)(out + off) = o2;
}

// ---------------- host launch sequence ----------------
extern "C" void kernel_launch(void* const* d_in, const int* in_sizes, int n_in,
                              void* d_out, int out_size) {
    const int*   adj_rows = (const int*)d_in[0];
    const int*   adj_cols = (const int*)d_in[1];
    const float* adj_vals = (const float*)d_in[2];
    const int*   img_rows = (const int*)d_in[3];
    const int*   img_cols = (const int*)d_in[4];
    const float* img_vals = (const float*)d_in[5];
    const int*   txt_rows = (const int*)d_in[6];
    const int*   txt_cols = (const int*)d_in[7];
    const float* txt_vals = (const float*)d_in[8];
    const float* u_emb    = (const float*)d_in[9];
    const float* i_emb    = (const float*)d_in[10];
    const float* img_W    = (const float*)d_in[11];
    const float* img_b    = (const float*)d_in[12];
    const float* txt_W    = (const float*)d_in[13];
    const float* txt_b    = (const float*)d_in[14];
    const float* modal_w  = (const float*)d_in[15];
    const float* att_w    = (const float*)d_in[16];
    const float* image_embedding = (const float*)d_in[17];
    const float* text_embedding  = (const float*)d_in[18];

    const int Eadj = in_sizes[0], Eimg = in_sizes[3], Etxt = in_sizes[6];
    int Emx = Eadj > Eimg ? Eadj : Eimg;
    if (Etxt > Emx) Emx = Etxt;

    float *e0, *Xtxt, *XimgI, *S1, *S2, *S3, *T1, *T2, *modal, *total, *Ebuf, *cur;
    float *scores, *red;
    int *counts, *rowptr, *woff, *bsums;
    int2 *colval;
    cudaGetSymbolAddress((void**)&e0,    g_e0);
    cudaGetSymbolAddress((void**)&Xtxt,  g_Xtxt);
    cudaGetSymbolAddress((void**)&XimgI, g_XimgI);
    cudaGetSymbolAddress((void**)&S1,    g_S1);
    cudaGetSymbolAddress((void**)&S2,    g_S2);
    cudaGetSymbolAddress((void**)&S3,    g_S3);
    cudaGetSymbolAddress((void**)&T1,    g_T1);
    cudaGetSymbolAddress((void**)&T2,    g_T2);
    cudaGetSymbolAddress((void**)&modal, g_modal);
    cudaGetSymbolAddress((void**)&total, g_total);
    cudaGetSymbolAddress((void**)&Ebuf,  g_E);
    cudaGetSymbolAddress((void**)&cur,   g_cur);
    cudaGetSymbolAddress((void**)&scores,g_scores);
    cudaGetSymbolAddress((void**)&red,   g_red);
    cudaGetSymbolAddress((void**)&counts,g_counts);
    cudaGetSymbolAddress((void**)&rowptr,g_rowptr);
    cudaGetSymbolAddress((void**)&woff,  g_woff);
    cudaGetSymbolAddress((void**)&bsums, g_bsums);
    cudaGetSymbolAddress((void**)&colval,g_colval);

    const int TPB = 256;
    const int ew_blocks   = (NN * DD + TPB - 1) / TPB;       // 25000
    const int row_blocks  = (NN * 32 + TPB - 1) / TPB;       // 12500 (warp/row)

    // ---- CSR build for 3 matrices ----
    cudaMemsetAsync(counts, 0, 3 * NN * sizeof(int));
    k_count3<<<(Emx + TPB - 1) / TPB, TPB>>>(adj_rows, img_rows, txt_rows, counts,
                                             Eadj, Eimg, Etxt);
    k_scan1<<<3 * NB, 256>>>(counts, bsums);
    k_scan2<<<1, 32>>>(bsums, rowptr);
    k_scan3<<<3 * NB, 256>>>(counts, bsums, rowptr, woff);
    k_scatter3<<<(Emx + TPB - 1) / TPB, TPB>>>(adj_rows, adj_cols, adj_vals,
                                               img_rows, img_cols, img_vals,
                                               txt_rows, txt_cols, txt_vals,
                                               woff, colval, Eadj, Eimg, Etxt);

    const int* rp_adj = rowptr + 0 * (NN + 1);
    const int* rp_img = rowptr + 1 * (NN + 1);
    const int* rp_txt = rowptr + 2 * (NN + 1);
    const int2* cv_adj = colval + (size_t)0 * EMAX;
    const int2* cv_img = colval + (size_t)1 * EMAX;
    const int2* cv_txt = colval + (size_t)2 * EMAX;

    // ---- dense projections + l2norm; e0 / Xtxt assembly ----
    k_concat<<<ew_blocks, TPB>>>(u_emb, i_emb, e0, Xtxt);
    k_gemm_norm<<<(UU + 63) / 64, 256>>>(image_embedding, img_W, img_b, XimgI, UU, 1024);
    k_gemm_norm<<<(UU + 63) / 64, 256>>>(text_embedding,  txt_W, txt_b,
                                         Xtxt + (size_t)UU * DD, UU, 384);

    // ---- modality SpMMs ----
    // S1 = spmm(img, e0); S3 = spmm(txt, e0)
    // S2 = spmm(adj, e0) [image branch], T1 = spmm(adj, Xtxt): fused dual-gather
    k_spmm<<<row_blocks, TPB>>>(rp_img, cv_img, e0, S1, nullptr, nullptr);
    k_spmm<<<row_blocks, TPB>>>(rp_txt, cv_txt, e0, S3, nullptr, nullptr);
    k_spmm2<<<row_blocks, TPB>>>(rp_adj, cv_adj, e0, Xtxt, S2, T1);
    // Y = concat(T1[:USER], i_embeds): e0's item half already holds i_embeds
    k_copy_u<<<(UU * DD + TPB - 1) / TPB, TPB>>>(T1, e0);
    k_spmm<<<row_blocks, TPB>>>(rp_adj, cv_adj, e0, T2, nullptr, nullptr);

    // ---- modal combine ----
    k_combine<<<ew_blocks, TPB>>>(u_emb, XimgI, S1, S2, S3, T1, T2, modal_w, modal, total);

    // ---- GNN layer 1 ----
    k_spmm<<<row_blocks, TPB>>>(rp_adj, cv_adj, modal, Ebuf, att_w + 0, scores);
    k_reduce<<<1, 1024>>>(scores, red);
    k_apply<<<ew_blocks, TPB>>>(Ebuf, scores, red, cur, total);
    // ---- GNN layer 2 ----
    k_spmm<<<row_blocks, TPB>>>(rp_adj, cv_adj, cur, Ebuf, att_w + DD, scores);
    k_reduce<<<1, 1024>>>(scores, red);
    k_apply<<<ew_blocks, TPB>>>(Ebuf, scores, red, cur, total);

    // ---- final: out = total + 0.5 * l2norm(modal) ----
    k_final<<<row_blocks, TPB>>>(modal, total, (float*)d_out);
}

// round 3
// speedup vs baseline: 1.2275x; 1.0965x over previous
#include <cuda_runtime.h>
#include <cuda_fp16.h>
#include <math.h>
#include <stdint.h>

// ---------------- problem constants ----------------
#define NN    100000          // USER + ITEM
#define UU    50000           // USER (== ITEM)
#define DD    64              // LATDIM
#define EMAX  3200000         // N_EDGES per matrix
#define LEAK  0.2f
#define RIS_ADJ_LAMBDA 0.2f
#define RIS_LAMBDA     0.5f

#define CHUNK 2048
#define NB    ((NN + CHUNK - 1) / CHUNK)   // 49 blocks per matrix for the scan

// ---------------- static scratch (no runtime alloc allowed) ----------------
__device__ __half g_e0h  [(size_t)NN*DD];   // concat(u,i) fp16        (spmm input)
__device__ __half g_e1h  [(size_t)NN*DD];   // concat(T1[:U], i) fp16  (spmm input)
__device__ __half g_Xth  [(size_t)NN*DD];   // concat(u, l2n(txtfeat)) (spmm input)
__device__ __half g_mh   [(size_t)NN*DD];   // modal fp16              (spmm input)
__device__ __half g_ch   [(size_t)NN*DD];   // cur fp16                (spmm input)
__device__ float g_XimgI[(size_t)UU*DD];
__device__ float g_S1   [(size_t)NN*DD];
__device__ float g_S2   [(size_t)NN*DD];
__device__ float g_S3   [(size_t)NN*DD];
__device__ float g_T1   [(size_t)NN*DD];
__device__ float g_T2   [(size_t)NN*DD];
__device__ float g_modal[(size_t)NN*DD];
__device__ float g_total[(size_t)NN*DD];
__device__ float g_E    [(size_t)NN*DD];
__device__ float g_scores[NN];
__device__ float g_red[2];
__device__ int   g_counts[3*NN];
__device__ int   g_rowptr[3*(NN+1)];
__device__ int   g_woff  [3*NN];
__device__ int   g_bsums [3*NB];
__device__ int2  g_colval[(size_t)3*EMAX];

// ---------------- f32x2 helpers (GEMM) ----------------
__device__ __forceinline__ unsigned long long pack2(float x, float y) {
    unsigned long long r;
    asm("mov.b64 %0, {%1,%2};" : "=l"(r) : "f"(x), "f"(y));
    return r;
}
__device__ __forceinline__ unsigned long long dup2(float v) { return pack2(v, v); }
__device__ __forceinline__ void unpack2(unsigned long long u, float& x, float& y) {
    asm("mov.b64 {%0,%1}, %2;" : "=f"(x), "=f"(y) : "l"(u));
}
__device__ __forceinline__ void ffma2(unsigned long long& d,
                                      unsigned long long a, unsigned long long b) {
    asm("fma.rn.f32x2 %0, %1, %2, %0;" : "+l"(d) : "l"(a), "l"(b));
}

// ---------------- CSR build ----------------
__global__ void k_count3(const int* __restrict__ r0, const int* __restrict__ r1,
                         const int* __restrict__ r2, int* __restrict__ cnt,
                         int e0, int e1, int e2) {
    int i = blockIdx.x * blockDim.x + threadIdx.x;
    if (i < e0) atomicAdd(&cnt[0 * NN + r0[i]], 1);
    if (i < e1) atomicAdd(&cnt[1 * NN + r1[i]], 1);
    if (i < e2) atomicAdd(&cnt[2 * NN + r2[i]], 1);
}

__global__ void k_scan1(const int* __restrict__ counts, int* __restrict__ bsums) {
    const int m = blockIdx.x / NB, b = blockIdx.x % NB;
    const int* c = counts + (size_t)m * NN;
    const int tid = threadIdx.x, lane = tid & 31, wid = tid >> 5;
    int base = b * CHUNK + tid * 8;
    int s = 0;
    #pragma unroll
    for (int k = 0; k < 8; k++) {
        int idx = base + k;
        if (idx < NN) s += c[idx];
    }
    #pragma unroll
    for (int o = 16; o; o >>= 1) s += __shfl_xor_sync(0xffffffffu, s, o);
    __shared__ int ws[8];
    if (lane == 0) ws[wid] = s;
    __syncthreads();
    if (tid == 0) {
        int t = 0;
        #pragma unroll
        for (int w = 0; w < 8; w++) t += ws[w];
        bsums[m * NB + b] = t;
    }
}

__global__ void k_scan2(int* __restrict__ bsums, int* __restrict__ rowptr) {
    int m = threadIdx.x;
    if (m >= 3) return;
    int* bs = bsums + m * NB;
    int v[NB];
    #pragma unroll
    for (int i = 0; i < NB; i++) v[i] = bs[i];
    int run = 0;
    #pragma unroll
    for (int i = 0; i < NB; i++) { int t = v[i]; bs[i] = run; run += t; }
    rowptr[(size_t)m * (NN + 1) + NN] = run;
}

__global__ void k_scan3(const int* __restrict__ counts, const int* __restrict__ bsums,
                        int* __restrict__ rowptr, int* __restrict__ woff) {
    const int m = blockIdx.x / NB, b = blockIdx.x % NB;
    const int* c = counts + (size_t)m * NN;
    int* rp = rowptr + (size_t)m * (NN + 1);
    int* wo = woff + (size_t)m * NN;
    const int tid = threadIdx.x, lane = tid & 31, wid = tid >> 5;
    int base = b * CHUNK + tid * 8;
    int v[8], pre[8];
    int s = 0;
    #pragma unroll
    for (int k = 0; k < 8; k++) {
        int idx = base + k;
        v[k] = (idx < NN) ? c[idx] : 0;
        s += v[k];
        pre[k] = s;
    }
    int tsum = s;
    int inc = tsum;
    #pragma unroll
    for (int o = 1; o < 32; o <<= 1) {
        int t = __shfl_up_sync(0xffffffffu, inc, o);
        if (lane >= o) inc += t;
    }
    __shared__ int ws[8];
    if (lane == 31) ws[wid] = inc;
    __syncthreads();
    int woffsum = 0;
    #pragma unroll
    for (int w = 0; w < 8; w++) woffsum += (w < wid) ? ws[w] : 0;
    int excl = bsums[m * NB + b] + woffsum + inc - tsum;
    #pragma unroll
    for (int k = 0; k < 8; k++) {
        int idx = base + k;
        if (idx < NN) {
            int e = excl + pre[k] - v[k];
            rp[idx] = e;
            wo[idx] = e;
        }
    }
}

__global__ void k_scatter3(const int* __restrict__ ar, const int* __restrict__ ac,
                           const float* __restrict__ av,
                           const int* __restrict__ ir, const int* __restrict__ ic,
                           const float* __restrict__ iv,
                           const int* __restrict__ tr, const int* __restrict__ tc,
                           const float* __restrict__ tv,
                           int* __restrict__ woff, int2* __restrict__ colval,
                           int e0, int e1, int e2) {
    int i = blockIdx.x * blockDim.x + threadIdx.x;
    if (i < e0) {
        int p = atomicAdd(&woff[0 * NN + ar[i]], 1);
        colval[(size_t)0 * EMAX + p] = make_int2(ac[i], __float_as_int(av[i]));
    }
    if (i < e1) {
        int p = atomicAdd(&woff[1 * NN + ir[i]], 1);
        colval[(size_t)1 * EMAX + p] = make_int2(ic[i], __float_as_int(iv[i]));
    }
    if (i < e2) {
        int p = atomicAdd(&woff[2 * NN + tr[i]], 1);
        colval[(size_t)2 * EMAX + p] = make_int2(tc[i], __float_as_int(tv[i]));
    }
}

// ---------------- SpMM (CSR gather, warp per row, fp16 x, fp32 acc) ----------
__device__ __forceinline__ void spmm_row(const int2* __restrict__ colval,
                                         const __half* __restrict__ x,
                                         int s, int e, int lane, float2& acc) {
    int base = s;
    for (; base + 32 <= e; base += 32) {
        int2 cv = colval[base + lane];
        #pragma unroll
        for (int j = 0; j < 32; j++) {
            int   c = __shfl_sync(0xffffffffu, cv.x, j);
            float v = __int_as_float(__shfl_sync(0xffffffffu, cv.y, j));
            float2 xv = __half22float2(*(const __half2*)(x + (size_t)c * DD + lane * 2));
            acc.x = fmaf(v, xv.x, acc.x);
            acc.y = fmaf(v, xv.y, acc.y);
        }
    }
    int rem = e - base;
    if (rem > 0) {
        int2 cv = (lane < rem) ? colval[base + lane] : make_int2(0, 0);
        for (int j = 0; j < rem; j++) {
            int   c = __shfl_sync(0xffffffffu, cv.x, j);
            float v = __int_as_float(__shfl_sync(0xffffffffu, cv.y, j));
            float2 xv = __half22float2(*(const __half2*)(x + (size_t)c * DD + lane * 2));
            acc.x = fmaf(v, xv.x, acc.x);
            acc.y = fmaf(v, xv.y, acc.y);
        }
    }
}

// generic single spmm with optional attention-score epilogue
__global__ void k_spmm(const int* __restrict__ rowptr, const int2* __restrict__ colval,
                       const __half* __restrict__ x, float* __restrict__ y,
                       const float* __restrict__ attw, float* __restrict__ scores) {
    int row = (blockIdx.x * blockDim.x + threadIdx.x) >> 5;
    if (row >= NN) return;
    const int lane = threadIdx.x & 31;
    float2 acc = make_float2(0.f, 0.f);
    spmm_row(colval, x, rowptr[row], rowptr[row + 1], lane, acc);
    *(float2*)(y + (size_t)row * DD + lane * 2) = acc;
    if (attw) {
        float sc = acc.x * attw[lane * 2] + acc.y * attw[lane * 2 + 1];
        #pragma unroll
        for (int o = 16; o; o >>= 1) sc += __shfl_xor_sync(0xffffffffu, sc, o);
        if (lane == 0) scores[row] = sc;
    }
}

// two independent matrices, same x: S1 = img@x, S3 = txt@x (one launch)
__global__ void k_spmm_2mat(const int* __restrict__ rp1, const int2* __restrict__ cv1,
                            const int* __restrict__ rp2, const int2* __restrict__ cv2,
                            const __half* __restrict__ x,
                            float* __restrict__ y1, float* __restrict__ y2) {
    int gr = (blockIdx.x * blockDim.x + threadIdx.x) >> 5;
    const int lane = threadIdx.x & 31;
    if (gr >= 2 * NN) return;
    int row = (gr < NN) ? gr : gr - NN;
    const int* rp = (gr < NN) ? rp1 : rp2;
    const int2* cv = (gr < NN) ? cv1 : cv2;
    float* y = (gr < NN) ? y1 : y2;
    float2 acc = make_float2(0.f, 0.f);
    spmm_row(cv, x, rp[row], rp[row + 1], lane, acc);
    *(float2*)(y + (size_t)row * DD + lane * 2) = acc;
}

// dual-input same matrix: y1 = A@x1, y2 = A@x2; also writes half(y2) user rows
// into e1h (input of the following T2 spmm).
__global__ void k_spmm2(const int* __restrict__ rowptr, const int2* __restrict__ colval,
                        const __half* __restrict__ x1, const __half* __restrict__ x2,
                        float* __restrict__ y1, float* __restrict__ y2,
                        __half* __restrict__ y2h_user) {
    int row = (blockIdx.x * blockDim.x + threadIdx.x) >> 5;
    if (row >= NN) return;
    const int lane = threadIdx.x & 31;
    const int s = rowptr[row], e = rowptr[row + 1];
    float2 a1 = make_float2(0.f, 0.f), a2 = make_float2(0.f, 0.f);
    int base = s;
    for (; base + 32 <= e; base += 32) {
        int2 cv = colval[base + lane];
        #pragma unroll
        for (int j = 0; j < 32; j++) {
            int   c = __shfl_sync(0xffffffffu, cv.x, j);
            float v = __int_as_float(__shfl_sync(0xffffffffu, cv.y, j));
            size_t off = (size_t)c * DD + lane * 2;
            float2 p = __half22float2(*(const __half2*)(x1 + off));
            float2 q = __half22float2(*(const __half2*)(x2 + off));
            a1.x = fmaf(v, p.x, a1.x); a1.y = fmaf(v, p.y, a1.y);
            a2.x = fmaf(v, q.x, a2.x); a2.y = fmaf(v, q.y, a2.y);
        }
    }
    int rem = e - base;
    if (rem > 0) {
        int2 cv = (lane < rem) ? colval[base + lane] : make_int2(0, 0);
        for (int j = 0; j < rem; j++) {
            int   c = __shfl_sync(0xffffffffu, cv.x, j);
            float v = __int_as_float(__shfl_sync(0xffffffffu, cv.y, j));
            size_t off = (size_t)c * DD + lane * 2;
            float2 p = __half22float2(*(const __half2*)(x1 + off));
            float2 q = __half22float2(*(const __half2*)(x2 + off));
            a1.x = fmaf(v, p.x, a1.x); a1.y = fmaf(v, p.y, a1.y);
            a2.x = fmaf(v, q.x, a2.x); a2.y = fmaf(v, q.y, a2.y);
        }
    }
    size_t off = (size_t)row * DD + lane * 2;
    *(float2*)(y1 + off) = a1;
    *(float2*)(y2 + off) = a2;
    if (row < UU) *(__half2*)(y2h_user + off) = __float22half2_rn(a2);
}

// ---------------- fused GEMM (M x K @ K x 64 + bias) + row l2norm ------------
// FFMA2 version; fp32 dst and/or fp16 dst.
__global__ void k_gemm_norm(const float* __restrict__ A, const float* __restrict__ W,
                            const float* __restrict__ bias,
                            float* __restrict__ dstf, __half* __restrict__ dsth,
                            int M, int K) {
    __shared__ unsigned long long As[64][17];
    __shared__ unsigned long long Bs[16][34];
    const int tid = threadIdx.x;
    const int tx = tid & 15;
    const int ty = tid >> 4;
    const int rowBase = blockIdx.x * 64;
    unsigned long long acc[4][2];
    #pragma unroll
    for (int i = 0; i < 4; i++) { acc[i][0] = 0ull; acc[i][1] = 0ull; }

    for (int kc = 0; kc < K; kc += 16) {
        {
            int r  = tid >> 2;
            int k4 = (tid & 3) * 4;
            float4 av = make_float4(0.f, 0.f, 0.f, 0.f);
            int gr = rowBase + r;
            if (gr < M) av = *(const float4*)&A[(size_t)gr * K + kc + k4];
            As[r][k4 + 0] = dup2(av.x); As[r][k4 + 1] = dup2(av.y);
            As[r][k4 + 2] = dup2(av.z); As[r][k4 + 3] = dup2(av.w);
        }
        {
            int kk = tid >> 4;
            int c4 = tid & 15;
            float4 w = *(const float4*)&W[(size_t)(kc + kk) * DD + c4 * 4];
            Bs[kk][2 * c4 + 0] = pack2(w.x, w.y);
            Bs[kk][2 * c4 + 1] = pack2(w.z, w.w);
        }
        __syncthreads();
        #pragma unroll
        for (int kk = 0; kk < 16; kk++) {
            unsigned long long a0 = As[ty][kk],      a1 = As[ty + 16][kk];
            unsigned long long a2 = As[ty + 32][kk], a3 = As[ty + 48][kk];
            longlong2 bb = *(const longlong2*)&Bs[kk][2 * tx];
            unsigned long long b0 = (unsigned long long)bb.x;
            unsigned long long b1 = (unsigned long long)bb.y;
            ffma2(acc[0][0], a0, b0); ffma2(acc[0][1], a0, b1);
            ffma2(acc[1][0], a1, b0); ffma2(acc[1][1], a1, b1);
            ffma2(acc[2][0], a2, b0); ffma2(acc[2][1], a2, b1);
            ffma2(acc[3][0], a3, b0); ffma2(acc[3][1], a3, b1);
        }
        __syncthreads();
    }
    float b0 = bias[tx * 4 + 0], b1 = bias[tx * 4 + 1];
    float b2 = bias[tx * 4 + 2], b3 = bias[tx * 4 + 3];
    #pragma unroll
    for (int i = 0; i < 4; i++) {
        float v0, v1, v2, v3;
        unpack2(acc[i][0], v0, v1);
        unpack2(acc[i][1], v2, v3);
        v0 += b0; v1 += b1; v2 += b2; v3 += b3;
        float ss = v0 * v0 + v1 * v1 + v2 * v2 + v3 * v3;
        #pragma unroll
        for (int o = 1; o < 16; o <<= 1) ss += __shfl_xor_sync(0xffffffffu, ss, o);
        float inv = 1.f / fmaxf(sqrtf(ss), 1e-12f);
        int gr = rowBase + ty + i * 16;
        if (gr < M) {
            size_t off = (size_t)gr * DD + tx * 4;
            if (dstf) {
                *(float4*)&dstf[off] = make_float4(v0 * inv, v1 * inv, v2 * inv, v3 * inv);
            }
            if (dsth) {
                __half2 h0 = __float22half2_rn(make_float2(v0 * inv, v1 * inv));
                __half2 h1 = __float22half2_rn(make_float2(v2 * inv, v3 * inv));
                *(__half2*)&dsth[off]     = h0;
                *(__half2*)&dsth[off + 2] = h1;
            }
        }
    }
}

// ---------------- elementwise glue ----------------
// e0h = half(concat(u,i)); e1h item half = half(i); Xth user half = half(u)
__global__ void k_concat(const float* __restrict__ u, const float* __restrict__ it,
                         __half* __restrict__ e0h, __half* __restrict__ e1h,
                         __half* __restrict__ Xth) {
    size_t idx2 = (size_t)blockIdx.x * blockDim.x + threadIdx.x;   // half2 index
    if (idx2 >= (size_t)NN * DD / 2) return;
    size_t idx = idx2 * 2;
    int n = (int)(idx >> 6);
    if (n < UU) {
        __half2 h = __float22half2_rn(*(const float2*)(u + idx));
        *(__half2*)(e0h + idx) = h;
        *(__half2*)(Xth + idx) = h;
    } else {
        __half2 h = __float22half2_rn(*(const float2*)(it + idx - (size_t)UU * DD));
        *(__half2*)(e0h + idx) = h;
        *(__half2*)(e1h + idx) = h;
    }
}

__global__ void k_combine(const float* __restrict__ u, const float* __restrict__ XimgI,
                          const float* __restrict__ S1, const float* __restrict__ S2,
                          const float* __restrict__ S3, const float* __restrict__ T1,
                          const float* __restrict__ T2, const float* __restrict__ mw,
                          float* __restrict__ modal, float* __restrict__ total,
                          __half* __restrict__ modalh) {
    size_t idx = (size_t)blockIdx.x * blockDim.x + threadIdx.x;
    if (idx >= (size_t)NN * DD) return;
    int n = (int)(idx >> 6);
    float a = mw[0], b = mw[1];
    float mx = fmaxf(a, b);
    float ea = expf(a - mx), eb = expf(b - mx);
    float w0 = ea / (ea + eb), w1 = eb / (ea + eb);
    float xi = (n < UU) ? u[idx] : XimgI[idx - (size_t)UU * DD];
    float ei = xi + S2[idx] + RIS_ADJ_LAMBDA * S1[idx];
    float et = T1[idx] + T2[idx] + RIS_ADJ_LAMBDA * S3[idx];
    float m = w0 * ei + w1 * et;
    modal[idx] = m;
    total[idx] = m;
    modalh[idx] = __float2half(m);
}

__global__ void k_reduce(const float* __restrict__ scores, float* __restrict__ red) {
    __shared__ float sm[32];
    const int tid = threadIdx.x, lane = tid & 31, wid = tid >> 5;
    float mx = -3.4e38f;
    for (int i = tid; i < NN; i += 1024) mx = fmaxf(mx, scores[i]);
    #pragma unroll
    for (int o = 16; o; o >>= 1) mx = fmaxf(mx, __shfl_xor_sync(0xffffffffu, mx, o));
    if (lane == 0) sm[wid] = mx;
    __syncthreads();
    if (wid == 0) {
        float m = sm[lane];
        #pragma unroll
        for (int o = 16; o; o >>= 1) m = fmaxf(m, __shfl_xor_sync(0xffffffffu, m, o));
        if (lane == 0) sm[0] = m;
    }
    __syncthreads();
    mx = sm[0];
    __syncthreads();
    float s = 0.f;
    for (int i = tid; i < NN; i += 1024) s += expf(scores[i] - mx);
    #pragma unroll
    for (int o = 16; o; o >>= 1) s += __shfl_xor_sync(0xffffffffu, s, o);
    if (lane == 0) sm[wid] = s;
    __syncthreads();
    if (wid == 0) {
        float t = sm[lane];
        #pragma unroll
        for (int o = 16; o; o >>= 1) t += __shfl_xor_sync(0xffffffffu, t, o);
        if (lane == 0) { red[0] = mx; red[1] = t; }
    }
}

__global__ void k_apply(const float* __restrict__ e, const float* __restrict__ scores,
                        const float* __restrict__ red, __half* __restrict__ curh,
                        float* __restrict__ total) {
    size_t idx = (size_t)blockIdx.x * blockDim.x + threadIdx.x;
    if (idx >= (size_t)NN * DD) return;
    int n = (int)(idx >> 6);
    float att = expf(scores[n] - red[0]) / red[1];
    float v = e[idx] * att;
    v = (v > 0.f) ? v : LEAK * v;
    curh[idx] = __float2half(v);
    total[idx] += v;
}

__global__ void k_final(const float* __restrict__ modal, const float* __restrict__ total,
                        float* __restrict__ out) {
    int row = (blockIdx.x * blockDim.x + threadIdx.x) >> 5;
    if (row >= NN) return;
    const int lane = threadIdx.x & 31;
    size_t off = (size_t)row * DD + lane * 2;
    float2 m = *(const float2*)(modal + off);
    float ss = m.x * m.x + m.y * m.y;
    #pragma unroll
    for (int o = 16; o; o >>= 1) ss += __shfl_xor_sync(0xffffffffu, ss, o);
    float inv = 1.f / fmaxf(sqrtf(ss), 1e-12f);
    float2 t = *(const float2*)(total + off);
    float2 o2 = make_float2(t.x + RIS_LAMBDA * m.x * inv,
                            t.y + RIS_LAMBDA * m.y * inv);
    *(float2*)(out + off) = o2;
}

// ---------------- host launch sequence ----------------
extern "C" void kernel_launch(void* const* d_in, const int* in_sizes, int n_in,
                              void* d_out, int out_size) {
    const int*   adj_rows = (const int*)d_in[0];
    const int*   adj_cols = (const int*)d_in[1];
    const float* adj_vals = (const float*)d_in[2];
    const int*   img_rows = (const int*)d_in[3];
    const int*   img_cols = (const int*)d_in[4];
    const float* img_vals = (const float*)d_in[5];
    const int*   txt_rows = (const int*)d_in[6];
    const int*   txt_cols = (const int*)d_in[7];
    const float* txt_vals = (const float*)d_in[8];
    const float* u_emb    = (const float*)d_in[9];
    const float* i_emb    = (const float*)d_in[10];
    const float* img_W    = (const float*)d_in[11];
    const float* img_b    = (const float*)d_in[12];
    const float* txt_W    = (const float*)d_in[13];
    const float* txt_b    = (const float*)d_in[14];
    const float* modal_w  = (const float*)d_in[15];
    const float* att_w    = (const float*)d_in[16];
    const float* image_embedding = (const float*)d_in[17];
    const float* text_embedding  = (const float*)d_in[18];

    const int Eadj = in_sizes[0], Eimg = in_sizes[3], Etxt = in_sizes[6];
    int Emx = Eadj > Eimg ? Eadj : Eimg;
    if (Etxt > Emx) Emx = Etxt;

    __half *e0h, *e1h, *Xth, *mh, *ch;
    float *XimgI, *S1, *S2, *S3, *T1, *T2, *modal, *total, *Ebuf;
    float *scores, *red;
    int *counts, *rowptr, *woff, *bsums;
    int2 *colval;
    cudaGetSymbolAddress((void**)&e0h,   g_e0h);
    cudaGetSymbolAddress((void**)&e1h,   g_e1h);
    cudaGetSymbolAddress((void**)&Xth,   g_Xth);
    cudaGetSymbolAddress((void**)&mh,    g_mh);
    cudaGetSymbolAddress((void**)&ch,    g_ch);
    cudaGetSymbolAddress((void**)&XimgI, g_XimgI);
    cudaGetSymbolAddress((void**)&S1,    g_S1);
    cudaGetSymbolAddress((void**)&S2,    g_S2);
    cudaGetSymbolAddress((void**)&S3,    g_S3);
    cudaGetSymbolAddress((void**)&T1,    g_T1);
    cudaGetSymbolAddress((void**)&T2,    g_T2);
    cudaGetSymbolAddress((void**)&modal, g_modal);
    cudaGetSymbolAddress((void**)&total, g_total);
    cudaGetSymbolAddress((void**)&Ebuf,  g_E);
    cudaGetSymbolAddress((void**)&scores,g_scores);
    cudaGetSymbolAddress((void**)&red,   g_red);
    cudaGetSymbolAddress((void**)&counts,g_counts);
    cudaGetSymbolAddress((void**)&rowptr,g_rowptr);
    cudaGetSymbolAddress((void**)&woff,  g_woff);
    cudaGetSymbolAddress((void**)&bsums, g_bsums);
    cudaGetSymbolAddress((void**)&colval,g_colval);

    const int TPB = 256;
    const int ew_blocks  = (NN * DD + TPB - 1) / TPB;
    const int ew2_blocks = (NN * DD / 2 + TPB - 1) / TPB;
    const int row_blocks = (NN * 32 + TPB - 1) / TPB;

    // ---- CSR build ----
    cudaMemsetAsync(counts, 0, 3 * NN * sizeof(int));
    k_count3<<<(Emx + TPB - 1) / TPB, TPB>>>(adj_rows, img_rows, txt_rows, counts,
                                             Eadj, Eimg, Etxt);
    k_scan1<<<3 * NB, 256>>>(counts, bsums);
    k_scan2<<<1, 32>>>(bsums, rowptr);
    k_scan3<<<3 * NB, 256>>>(counts, bsums, rowptr, woff);
    k_scatter3<<<(Emx + TPB - 1) / TPB, TPB>>>(adj_rows, adj_cols, adj_vals,
                                               img_rows, img_cols, img_vals,
                                               txt_rows, txt_cols, txt_vals,
                                               woff, colval, Eadj, Eimg, Etxt);

    const int* rp_adj = rowptr + 0 * (NN + 1);
    const int* rp_img = rowptr + 1 * (NN + 1);
    const int* rp_txt = rowptr + 2 * (NN + 1);
    const int2* cv_adj = colval + (size_t)0 * EMAX;
    const int2* cv_img = colval + (size_t)1 * EMAX;
    const int2* cv_txt = colval + (size_t)2 * EMAX;

    // ---- dense projections + l2norm; half input assembly ----
    k_concat<<<ew2_blocks, TPB>>>(u_emb, i_emb, e0h, e1h, Xth);
    k_gemm_norm<<<(UU + 63) / 64, 256>>>(image_embedding, img_W, img_b,
                                         XimgI, nullptr, UU, 1024);
    k_gemm_norm<<<(UU + 63) / 64, 256>>>(text_embedding, txt_W, txt_b,
                                         nullptr, Xth + (size_t)UU * DD, UU, 384);

    // ---- modality SpMMs (fp16 gather) ----
    k_spmm_2mat<<<2 * row_blocks, TPB>>>(rp_img, cv_img, rp_txt, cv_txt, e0h, S1, S3);
    k_spmm2<<<row_blocks, TPB>>>(rp_adj, cv_adj, e0h, Xth, S2, T1, e1h);
    k_spmm<<<row_blocks, TPB>>>(rp_adj, cv_adj, e1h, T2, nullptr, nullptr);

    // ---- modal combine ----
    k_combine<<<ew_blocks, TPB>>>(u_emb, XimgI, S1, S2, S3, T1, T2, modal_w,
                                  modal, total, mh);

    // ---- GNN layers ----
    k_spmm<<<row_blocks, TPB>>>(rp_adj, cv_adj, mh, Ebuf, att_w + 0, scores);
    k_reduce<<<1, 1024>>>(scores, red);
    k_apply<<<ew_blocks, TPB>>>(Ebuf, scores, red, ch, total);
    k_spmm<<<row_blocks, TPB>>>(rp_adj, cv_adj, ch, Ebuf, att_w + DD, scores);
    k_reduce<<<1, 1024>>>(scores, red);
    k_apply<<<ew_blocks, TPB>>>(Ebuf, scores, red, ch, total);

    // ---- final ----
    k_final<<<row_blocks, TPB>>>(modal, total, (float*)d_out);
}

// round 4
// speedup vs baseline: 1.2987x; 1.0580x over previous
#include <cuda_runtime.h>
#include <cuda_fp16.h>
#include <math.h>
#include <stdint.h>

// ---------------- problem constants ----------------
#define NN    100000          // USER + ITEM
#define UU    50000           // USER (== ITEM)
#define DD    64              // LATDIM
#define EMAX  3200000         // N_EDGES per matrix
#define LEAK  0.2f
#define RIS_ADJ_LAMBDA 0.2f
#define RIS_LAMBDA     0.5f

#define CHUNK 2048
#define NB    ((NN + CHUNK - 1) / CHUNK)   // 49 scan blocks per matrix

// ---------------- static scratch ----------------
__device__ __half g_e0h  [(size_t)NN*DD];   // concat(u,i) fp16
__device__ __half g_e1h  [(size_t)NN*DD];   // concat(T1[:U], i) fp16
__device__ __half g_Xth  [(size_t)NN*DD];   // concat(u, l2n(txtfeat)) fp16
__device__ __half g_mh   [(size_t)NN*DD];   // modal fp16
__device__ __half g_ch   [(size_t)NN*DD];   // cur fp16
__device__ float g_XimgI[(size_t)UU*DD];
__device__ float g_S1   [(size_t)NN*DD];
__device__ float g_S2   [(size_t)NN*DD];
__device__ float g_S3   [(size_t)NN*DD];
__device__ float g_T1   [(size_t)NN*DD];
__device__ float g_modal[(size_t)NN*DD];
__device__ float g_total[(size_t)NN*DD];
__device__ float g_E    [(size_t)NN*DD];
__device__ float g_scores[NN];
__device__ float g_red[2];
__device__ int   g_counts[3*NN];            // zero-init at load; re-zeroed by k_scan3f
__device__ int   g_rowptr[3*(NN+1)];
__device__ int   g_woff  [3*NN];
__device__ int   g_bsums [3*NB];
__device__ int2  g_colval[(size_t)3*EMAX];

// ---------------- f32x2 helpers (GEMM) ----------------
__device__ __forceinline__ unsigned long long pack2(float x, float y) {
    unsigned long long r;
    asm("mov.b64 %0, {%1,%2};" : "=l"(r) : "f"(x), "f"(y));
    return r;
}
__device__ __forceinline__ unsigned long long dup2(float v) { return pack2(v, v); }
__device__ __forceinline__ void unpack2(unsigned long long u, float& x, float& y) {
    asm("mov.b64 {%0,%1}, %2;" : "=f"(x), "=f"(y) : "l"(u));
}
__device__ __forceinline__ void ffma2(unsigned long long& d,
                                      unsigned long long a, unsigned long long b) {
    asm("fma.rn.f32x2 %0, %1, %2, %0;" : "+l"(d) : "l"(a), "l"(b));
}

// ---------------- launch 1: count (3 matrices) + fp16 concat ----------------
// grid sized for max(edges, NN*DD/2) indices
__global__ void k_count3_concat(const int* __restrict__ r0, const int* __restrict__ r1,
                                const int* __restrict__ r2, int* __restrict__ cnt,
                                int e0, int e1, int e2,
                                const float* __restrict__ u, const float* __restrict__ it,
                                __half* __restrict__ e0h, __half* __restrict__ e1h,
                                __half* __restrict__ Xth) {
    int i = blockIdx.x * blockDim.x + threadIdx.x;
    if (i < e0) atomicAdd(&cnt[0 * NN + r0[i]], 1);
    if (i < e1) atomicAdd(&cnt[1 * NN + r1[i]], 1);
    if (i < e2) atomicAdd(&cnt[2 * NN + r2[i]], 1);
    size_t idx2 = (size_t)i;
    if (idx2 < (size_t)NN * DD / 2) {
        size_t idx = idx2 * 2;
        int n = (int)(idx >> 6);
        if (n < UU) {
            __half2 h = __float22half2_rn(*(const float2*)(u + idx));
            *(__half2*)(e0h + idx) = h;
            *(__half2*)(Xth + idx) = h;
        } else {
            __half2 h = __float22half2_rn(*(const float2*)(it + idx - (size_t)UU * DD));
            *(__half2*)(e0h + idx) = h;
            *(__half2*)(e1h + idx) = h;
        }
    }
}

// ---------------- launch 2: per-block sums ----------------
__global__ void k_scan1(const int* __restrict__ counts, int* __restrict__ bsums) {
    const int m = blockIdx.x / NB, b = blockIdx.x % NB;
    const int* c = counts + (size_t)m * NN;
    const int tid = threadIdx.x, lane = tid & 31, wid = tid >> 5;
    int base = b * CHUNK + tid * 8;
    int s = 0;
    #pragma unroll
    for (int k = 0; k < 8; k++) {
        int idx = base + k;
        if (idx < NN) s += c[idx];
    }
    #pragma unroll
    for (int o = 16; o; o >>= 1) s += __shfl_xor_sync(0xffffffffu, s, o);
    __shared__ int ws[8];
    if (lane == 0) ws[wid] = s;
    __syncthreads();
    if (tid == 0) {
        int t = 0;
        #pragma unroll
        for (int w = 0; w < 8; w++) t += ws[w];
        bsums[m * NB + b] = t;
    }
}

// ---------------- launch 3: rescan (block prefix in-smem) + zero counts ------
__global__ void k_scan3f(int* __restrict__ counts, const int* __restrict__ bsums,
                         int* __restrict__ rowptr, int* __restrict__ woff) {
    const int m = blockIdx.x / NB, b = blockIdx.x % NB;
    int* c = counts + (size_t)m * NN;
    int* rp = rowptr + (size_t)m * (NN + 1);
    int* wo = woff + (size_t)m * NN;
    const int tid = threadIdx.x, lane = tid & 31, wid = tid >> 5;

    __shared__ int sb[NB];
    if (tid < NB) sb[tid] = bsums[m * NB + tid];
    __syncthreads();
    int blockoff = 0;
    for (int i = 0; i < b; i++) blockoff += sb[i];
    if (b == 0 && tid == 0) {
        int tot = 0;
        for (int i = 0; i < NB; i++) tot += sb[i];
        rp[NN] = tot;
    }

    int base = b * CHUNK + tid * 8;
    int v[8], pre[8];
    int s = 0;
    #pragma unroll
    for (int k = 0; k < 8; k++) {
        int idx = base + k;
        v[k] = (idx < NN) ? c[idx] : 0;
        if (idx < NN) c[idx] = 0;           // re-zero for the next replay
        s += v[k];
        pre[k] = s;
    }
    int tsum = s;
    int inc = tsum;
    #pragma unroll
    for (int o = 1; o < 32; o <<= 1) {
        int t = __shfl_up_sync(0xffffffffu, inc, o);
        if (lane >= o) inc += t;
    }
    __shared__ int ws[8];
    if (lane == 31) ws[wid] = inc;
    __syncthreads();
    int woffsum = 0;
    #pragma unroll
    for (int w = 0; w < 8; w++) woffsum += (w < wid) ? ws[w] : 0;
    int excl = blockoff + woffsum + inc - tsum;
    #pragma unroll
    for (int k = 0; k < 8; k++) {
        int idx = base + k;
        if (idx < NN) {
            int e = excl + pre[k] - v[k];
            rp[idx] = e;
            wo[idx] = e;
        }
    }
}

// ---------------- launch 4: scatter edges into CSR slots ----------------
__global__ void k_scatter3(const int* __restrict__ ar, const int* __restrict__ ac,
                           const float* __restrict__ av,
                           const int* __restrict__ ir, const int* __restrict__ ic,
                           const float* __restrict__ iv,
                           const int* __restrict__ tr, const int* __restrict__ tc,
                           const float* __restrict__ tv,
                           int* __restrict__ woff, int2* __restrict__ colval,
                           int e0, int e1, int e2) {
    int i = blockIdx.x * blockDim.x + threadIdx.x;
    if (i < e0) {
        int p = atomicAdd(&woff[0 * NN + ar[i]], 1);
        colval[(size_t)0 * EMAX + p] = make_int2(ac[i], __float_as_int(av[i]));
    }
    if (i < e1) {
        int p = atomicAdd(&woff[1 * NN + ir[i]], 1);
        colval[(size_t)1 * EMAX + p] = make_int2(ic[i], __float_as_int(iv[i]));
    }
    if (i < e2) {
        int p = atomicAdd(&woff[2 * NN + tr[i]], 1);
        colval[(size_t)2 * EMAX + p] = make_int2(tc[i], __float_as_int(tv[i]));
    }
}

// ---------------- SpMM core (CSR gather, warp per row, fp16 x, fp32 acc) -----
__device__ __forceinline__ void spmm_row(const int2* __restrict__ colval,
                                         const __half* __restrict__ x,
                                         int s, int e, int lane, float2& acc) {
    int base = s;
    for (; base + 32 <= e; base += 32) {
        int2 cv = colval[base + lane];
        #pragma unroll
        for (int j = 0; j < 32; j++) {
            int   c = __shfl_sync(0xffffffffu, cv.x, j);
            float v = __int_as_float(__shfl_sync(0xffffffffu, cv.y, j));
            float2 xv = __half22float2(*(const __half2*)(x + (size_t)c * DD + lane * 2));
            acc.x = fmaf(v, xv.x, acc.x);
            acc.y = fmaf(v, xv.y, acc.y);
        }
    }
    int rem = e - base;
    if (rem > 0) {
        int2 cv = (lane < rem) ? colval[base + lane] : make_int2(0, 0);
        for (int j = 0; j < rem; j++) {
            int   c = __shfl_sync(0xffffffffu, cv.x, j);
            float v = __int_as_float(__shfl_sync(0xffffffffu, cv.y, j));
            float2 xv = __half22float2(*(const __half2*)(x + (size_t)c * DD + lane * 2));
            acc.x = fmaf(v, xv.x, acc.x);
            acc.y = fmaf(v, xv.y, acc.y);
        }
    }
}

// launch 5 (PROFILED): S1 = img@e0h, S3 = txt@e0h in one grid
__global__ void k_spmm_2mat(const int* __restrict__ rp1, const int2* __restrict__ cv1,
                            const int* __restrict__ rp2, const int2* __restrict__ cv2,
                            const __half* __restrict__ x,
                            float* __restrict__ y1, float* __restrict__ y2) {
    int gr = (blockIdx.x * blockDim.x + threadIdx.x) >> 5;
    const int lane = threadIdx.x & 31;
    if (gr >= 2 * NN) return;
    int row = (gr < NN) ? gr : gr - NN;
    const int* rp = (gr < NN) ? rp1 : rp2;
    const int2* cv = (gr < NN) ? cv1 : cv2;
    float* y = (gr < NN) ? y1 : y2;
    float2 acc = make_float2(0.f, 0.f);
    spmm_row(cv, x, rp[row], rp[row + 1], lane, acc);
    *(float2*)(y + (size_t)row * DD + lane * 2) = acc;
}

// generic single spmm with optional attention-score epilogue
__global__ void k_spmm(const int* __restrict__ rowptr, const int2* __restrict__ colval,
                       const __half* __restrict__ x, float* __restrict__ y,
                       const float* __restrict__ attw, float* __restrict__ scores) {
    int row = (blockIdx.x * blockDim.x + threadIdx.x) >> 5;
    if (row >= NN) return;
    const int lane = threadIdx.x & 31;
    float2 acc = make_float2(0.f, 0.f);
    spmm_row(colval, x, rowptr[row], rowptr[row + 1], lane, acc);
    *(float2*)(y + (size_t)row * DD + lane * 2) = acc;
    if (attw) {
        float sc = acc.x * attw[lane * 2] + acc.y * attw[lane * 2 + 1];
        #pragma unroll
        for (int o = 16; o; o >>= 1) sc += __shfl_xor_sync(0xffffffffu, sc, o);
        if (lane == 0) scores[row] = sc;
    }
}

// dual-input same matrix: S2 = adj@e0h, T1 = adj@Xth; also e1h user rows = half(T1)
__global__ void k_spmm2(const int* __restrict__ rowptr, const int2* __restrict__ colval,
                        const __half* __restrict__ x1, const __half* __restrict__ x2,
                        float* __restrict__ y1, float* __restrict__ y2,
                        __half* __restrict__ y2h_user) {
    int row = (blockIdx.x * blockDim.x + threadIdx.x) >> 5;
    if (row >= NN) return;
    const int lane = threadIdx.x & 31;
    const int s = rowptr[row], e = rowptr[row + 1];
    float2 a1 = make_float2(0.f, 0.f), a2 = make_float2(0.f, 0.f);
    int base = s;
    for (; base + 32 <= e; base += 32) {
        int2 cv = colval[base + lane];
        #pragma unroll
        for (int j = 0; j < 32; j++) {
            int   c = __shfl_sync(0xffffffffu, cv.x, j);
            float v = __int_as_float(__shfl_sync(0xffffffffu, cv.y, j));
            size_t off = (size_t)c * DD + lane * 2;
            float2 p = __half22float2(*(const __half2*)(x1 + off));
            float2 q = __half22float2(*(const __half2*)(x2 + off));
            a1.x = fmaf(v, p.x, a1.x); a1.y = fmaf(v, p.y, a1.y);
            a2.x = fmaf(v, q.x, a2.x); a2.y = fmaf(v, q.y, a2.y);
        }
    }
    int rem = e - base;
    if (rem > 0) {
        int2 cv = (lane < rem) ? colval[base + lane] : make_int2(0, 0);
        for (int j = 0; j < rem; j++) {
            int   c = __shfl_sync(0xffffffffu, cv.x, j);
            float v = __int_as_float(__shfl_sync(0xffffffffu, cv.y, j));
            size_t off = (size_t)c * DD + lane * 2;
            float2 p = __half22float2(*(const __half2*)(x1 + off));
            float2 q = __half22float2(*(const __half2*)(x2 + off));
            a1.x = fmaf(v, p.x, a1.x); a1.y = fmaf(v, p.y, a1.y);
            a2.x = fmaf(v, q.x, a2.x); a2.y = fmaf(v, q.y, a2.y);
        }
    }
    size_t off = (size_t)row * DD + lane * 2;
    *(float2*)(y1 + off) = a1;
    *(float2*)(y2 + off) = a2;
    if (row < UU) *(__half2*)(y2h_user + off) = __float22half2_rn(a2);
}

// T2 = adj@e1h, fused with the modal-combine epilogue (T2 never hits memory)
__global__ void k_spmmT2_combine(const int* __restrict__ rowptr,
                                 const int2* __restrict__ colval,
                                 const __half* __restrict__ x,
                                 const float* __restrict__ u,
                                 const float* __restrict__ XimgI,
                                 const float* __restrict__ S1,
                                 const float* __restrict__ S2,
                                 const float* __restrict__ S3,
                                 const float* __restrict__ T1,
                                 const float* __restrict__ mw,
                                 float* __restrict__ modal, float* __restrict__ total,
                                 __half* __restrict__ modalh) {
    int row = (blockIdx.x * blockDim.x + threadIdx.x) >> 5;
    if (row >= NN) return;
    const int lane = threadIdx.x & 31;
    float2 t2 = make_float2(0.f, 0.f);
    spmm_row(colval, x, rowptr[row], rowptr[row + 1], lane, t2);

    float a = mw[0], b = mw[1];
    float mx = fmaxf(a, b);
    float ea = expf(a - mx), eb = expf(b - mx);
    float w0 = ea / (ea + eb), w1 = eb / (ea + eb);

    size_t off = (size_t)row * DD + lane * 2;
    float2 s1 = *(const float2*)(S1 + off);
    float2 s2 = *(const float2*)(S2 + off);
    float2 s3 = *(const float2*)(S3 + off);
    float2 t1 = *(const float2*)(T1 + off);
    float2 xi = (row < UU) ? *(const float2*)(u + off)
                           : *(const float2*)(XimgI + off - (size_t)UU * DD);
    float eix = xi.x + s2.x + RIS_ADJ_LAMBDA * s1.x;
    float eiy = xi.y + s2.y + RIS_ADJ_LAMBDA * s1.y;
    float etx = t1.x + t2.x + RIS_ADJ_LAMBDA * s3.x;
    float ety = t1.y + t2.y + RIS_ADJ_LAMBDA * s3.y;
    float2 m = make_float2(w0 * eix + w1 * etx, w0 * eiy + w1 * ety);
    *(float2*)(modal + off) = m;
    *(float2*)(total + off) = m;
    *(__half2*)(modalh + off) = __float22half2_rn(m);
}

// ---------------- fused GEMM (M x K @ K x 64 + bias) + row l2norm ------------
__global__ void k_gemm_norm(const float* __restrict__ A, const float* __restrict__ W,
                            const float* __restrict__ bias,
                            float* __restrict__ dstf, __half* __restrict__ dsth,
                            int M, int K) {
    __shared__ unsigned long long As[64][17];
    __shared__ unsigned long long Bs[16][34];
    const int tid = threadIdx.x;
    const int tx = tid & 15;
    const int ty = tid >> 4;
    const int rowBase = blockIdx.x * 64;
    unsigned long long acc[4][2];
    #pragma unroll
    for (int i = 0; i < 4; i++) { acc[i][0] = 0ull; acc[i][1] = 0ull; }

    for (int kc = 0; kc < K; kc += 16) {
        {
            int r  = tid >> 2;
            int k4 = (tid & 3) * 4;
            float4 av = make_float4(0.f, 0.f, 0.f, 0.f);
            int gr = rowBase + r;
            if (gr < M) av = *(const float4*)&A[(size_t)gr * K + kc + k4];
            As[r][k4 + 0] = dup2(av.x); As[r][k4 + 1] = dup2(av.y);
            As[r][k4 + 2] = dup2(av.z); As[r][k4 + 3] = dup2(av.w);
        }
        {
            int kk = tid >> 4;
            int c4 = tid & 15;
            float4 w = *(const float4*)&W[(size_t)(kc + kk) * DD + c4 * 4];
            Bs[kk][2 * c4 + 0] = pack2(w.x, w.y);
            Bs[kk][2 * c4 + 1] = pack2(w.z, w.w);
        }
        __syncthreads();
        #pragma unroll
        for (int kk = 0; kk < 16; kk++) {
            unsigned long long a0 = As[ty][kk],      a1 = As[ty + 16][kk];
            unsigned long long a2 = As[ty + 32][kk], a3 = As[ty + 48][kk];
            longlong2 bb = *(const longlong2*)&Bs[kk][2 * tx];
            unsigned long long b0 = (unsigned long long)bb.x;
            unsigned long long b1 = (unsigned long long)bb.y;
            ffma2(acc[0][0], a0, b0); ffma2(acc[0][1], a0, b1);
            ffma2(acc[1][0], a1, b0); ffma2(acc[1][1], a1, b1);
            ffma2(acc[2][0], a2, b0); ffma2(acc[2][1], a2, b1);
            ffma2(acc[3][0], a3, b0); ffma2(acc[3][1], a3, b1);
        }
        __syncthreads();
    }
    float b0 = bias[tx * 4 + 0], b1 = bias[tx * 4 + 1];
    float b2 = bias[tx * 4 + 2], b3 = bias[tx * 4 + 3];
    #pragma unroll
    for (int i = 0; i < 4; i++) {
        float v0, v1, v2, v3;
        unpack2(acc[i][0], v0, v1);
        unpack2(acc[i][1], v2, v3);
        v0 += b0; v1 += b1; v2 += b2; v3 += b3;
        float ss = v0 * v0 + v1 * v1 + v2 * v2 + v3 * v3;
        #pragma unroll
        for (int o = 1; o < 16; o <<= 1) ss += __shfl_xor_sync(0xffffffffu, ss, o);
        float inv = 1.f / fmaxf(sqrtf(ss), 1e-12f);
        int gr = rowBase + ty + i * 16;
        if (gr < M) {
            size_t off = (size_t)gr * DD + tx * 4;
            if (dstf) {
                *(float4*)&dstf[off] = make_float4(v0 * inv, v1 * inv, v2 * inv, v3 * inv);
            }
            if (dsth) {
                *(__half2*)&dsth[off]     = __float22half2_rn(make_float2(v0 * inv, v1 * inv));
                *(__half2*)&dsth[off + 2] = __float22half2_rn(make_float2(v2 * inv, v3 * inv));
            }
        }
    }
}

// ---------------- softmax reduce + apply ----------------
__global__ void k_reduce(const float* __restrict__ scores, float* __restrict__ red) {
    __shared__ float sm[32];
    const int tid = threadIdx.x, lane = tid & 31, wid = tid >> 5;
    float mx = -3.4e38f;
    for (int i = tid; i < NN; i += 1024) mx = fmaxf(mx, scores[i]);
    #pragma unroll
    for (int o = 16; o; o >>= 1) mx = fmaxf(mx, __shfl_xor_sync(0xffffffffu, mx, o));
    if (lane == 0) sm[wid] = mx;
    __syncthreads();
    if (wid == 0) {
        float m = sm[lane];
        #pragma unroll
        for (int o = 16; o; o >>= 1) m = fmaxf(m, __shfl_xor_sync(0xffffffffu, m, o));
        if (lane == 0) sm[0] = m;
    }
    __syncthreads();
    mx = sm[0];
    __syncthreads();
    float s = 0.f;
    for (int i = tid; i < NN; i += 1024) s += expf(scores[i] - mx);
    #pragma unroll
    for (int o = 16; o; o >>= 1) s += __shfl_xor_sync(0xffffffffu, s, o);
    if (lane == 0) sm[wid] = s;
    __syncthreads();
    if (wid == 0) {
        float t = sm[lane];
        #pragma unroll
        for (int o = 16; o; o >>= 1) t += __shfl_xor_sync(0xffffffffu, t, o);
        if (lane == 0) { red[0] = mx; red[1] = t; }
    }
}

// layer-1 apply: cur (fp16) + total accumulation
__global__ void k_apply(const float* __restrict__ e, const float* __restrict__ scores,
                        const float* __restrict__ red, __half* __restrict__ curh,
                        float* __restrict__ total) {
    size_t idx = (size_t)blockIdx.x * blockDim.x + threadIdx.x;
    if (idx >= (size_t)NN * DD) return;
    int n = (int)(idx >> 6);
    float att = expf(scores[n] - red[0]) / red[1];
    float v = e[idx] * att;
    v = (v > 0.f) ? v : LEAK * v;
    curh[idx] = __float2half(v);
    total[idx] += v;
}

// layer-2 apply fused with the final l2norm output (warp per row)
__global__ void k_apply2_final(const float* __restrict__ e, const float* __restrict__ scores,
                               const float* __restrict__ red,
                               const float* __restrict__ total,
                               const float* __restrict__ modal,
                               float* __restrict__ out) {
    int row = (blockIdx.x * blockDim.x + threadIdx.x) >> 5;
    if (row >= NN) return;
    const int lane = threadIdx.x & 31;
    size_t off = (size_t)row * DD + lane * 2;
    float att = expf(scores[row] - red[0]) / red[1];
    float2 ev = *(const float2*)(e + off);
    float vx = ev.x * att; vx = (vx > 0.f) ? vx : LEAK * vx;
    float vy = ev.y * att; vy = (vy > 0.f) ? vy : LEAK * vy;
    float2 t = *(const float2*)(total + off);
    t.x += vx; t.y += vy;
    float2 m = *(const float2*)(modal + off);
    float ss = m.x * m.x + m.y * m.y;
    #pragma unroll
    for (int o = 16; o; o >>= 1) ss += __shfl_xor_sync(0xffffffffu, ss, o);
    float inv = 1.f / fmaxf(sqrtf(ss), 1e-12f);
    *(float2*)(out + off) = make_float2(t.x + RIS_LAMBDA * m.x * inv,
                                        t.y + RIS_LAMBDA * m.y * inv);
}

// ---------------- host launch sequence ----------------
extern "C" void kernel_launch(void* const* d_in, const int* in_sizes, int n_in,
                              void* d_out, int out_size) {
    const int*   adj_rows = (const int*)d_in[0];
    const int*   adj_cols = (const int*)d_in[1];
    const float* adj_vals = (const float*)d_in[2];
    const int*   img_rows = (const int*)d_in[3];
    const int*   img_cols = (const int*)d_in[4];
    const float* img_vals = (const float*)d_in[5];
    const int*   txt_rows = (const int*)d_in[6];
    const int*   txt_cols = (const int*)d_in[7];
    const float* txt_vals = (const float*)d_in[8];
    const float* u_emb    = (const float*)d_in[9];
    const float* i_emb    = (const float*)d_in[10];
    const float* img_W    = (const float*)d_in[11];
    const float* img_b    = (const float*)d_in[12];
    const float* txt_W    = (const float*)d_in[13];
    const float* txt_b    = (const float*)d_in[14];
    const float* modal_w  = (const float*)d_in[15];
    const float* att_w    = (const float*)d_in[16];
    const float* image_embedding = (const float*)d_in[17];
    const float* text_embedding  = (const float*)d_in[18];

    const int Eadj = in_sizes[0], Eimg = in_sizes[3], Etxt = in_sizes[6];
    int Emx = Eadj > Eimg ? Eadj : Eimg;
    if (Etxt > Emx) Emx = Etxt;
    long long fuse_n = (long long)NN * DD / 2;
    if ((long long)Emx > fuse_n) fuse_n = Emx;

    __half *e0h, *e1h, *Xth, *mh, *ch;
    float *XimgI, *S1, *S2, *S3, *T1, *modal, *total, *Ebuf;
    float *scores, *red;
    int *counts, *rowptr, *woff, *bsums;
    int2 *colval;
    cudaGetSymbolAddress((void**)&e0h,   g_e0h);
    cudaGetSymbolAddress((void**)&e1h,   g_e1h);
    cudaGetSymbolAddress((void**)&Xth,   g_Xth);
    cudaGetSymbolAddress((void**)&mh,    g_mh);
    cudaGetSymbolAddress((void**)&ch,    g_ch);
    cudaGetSymbolAddress((void**)&XimgI, g_XimgI);
    cudaGetSymbolAddress((void**)&S1,    g_S1);
    cudaGetSymbolAddress((void**)&S2,    g_S2);
    cudaGetSymbolAddress((void**)&S3,    g_S3);
    cudaGetSymbolAddress((void**)&T1,    g_T1);
    cudaGetSymbolAddress((void**)&modal, g_modal);
    cudaGetSymbolAddress((void**)&total, g_total);
    cudaGetSymbolAddress((void**)&Ebuf,  g_E);
    cudaGetSymbolAddress((void**)&scores,g_scores);
    cudaGetSymbolAddress((void**)&red,   g_red);
    cudaGetSymbolAddress((void**)&counts,g_counts);
    cudaGetSymbolAddress((void**)&rowptr,g_rowptr);
    cudaGetSymbolAddress((void**)&woff,  g_woff);
    cudaGetSymbolAddress((void**)&bsums, g_bsums);
    cudaGetSymbolAddress((void**)&colval,g_colval);

    const int TPB = 256;
    const int ew_blocks   = (NN * DD + TPB - 1) / TPB;
    const int row_blocks  = (NN * 32 + TPB - 1) / TPB;
    const int fuse_blocks = (int)((fuse_n + TPB - 1) / TPB);

    const int* rp_adj = rowptr + 0 * (NN + 1);
    const int* rp_img = rowptr + 1 * (NN + 1);
    const int* rp_txt = rowptr + 2 * (NN + 1);
    const int2* cv_adj = colval + (size_t)0 * EMAX;
    const int2* cv_img = colval + (size_t)1 * EMAX;
    const int2* cv_txt = colval + (size_t)2 * EMAX;

    // 1: count + fp16 concat  (counts pre-zeroed: load-time init / k_scan3f re-zero)
    k_count3_concat<<<fuse_blocks, TPB>>>(adj_rows, img_rows, txt_rows, counts,
                                          Eadj, Eimg, Etxt,
                                          u_emb, i_emb, e0h, e1h, Xth);
    // 2-3: scan
    k_scan1<<<3 * NB, 256>>>(counts, bsums);
    k_scan3f<<<3 * NB, 256>>>(counts, bsums, rowptr, woff);
    // 4: scatter
    k_scatter3<<<(Emx + TPB - 1) / TPB, TPB>>>(adj_rows, adj_cols, adj_vals,
                                               img_rows, img_cols, img_vals,
                                               txt_rows, txt_cols, txt_vals,
                                               woff, colval, Eadj, Eimg, Etxt);
    // 5 (profiled): S1 = img@e0h, S3 = txt@e0h
    k_spmm_2mat<<<2 * row_blocks, TPB>>>(rp_img, cv_img, rp_txt, cv_txt, e0h, S1, S3);
    // 6-7: dense projections + l2norm
    k_gemm_norm<<<(UU + 63) / 64, 256>>>(image_embedding, img_W, img_b,
                                         XimgI, nullptr, UU, 1024);
    k_gemm_norm<<<(UU + 63) / 64, 256>>>(text_embedding, txt_W, txt_b,
                                         nullptr, Xth + (size_t)UU * DD, UU, 384);
    // 8: S2 = adj@e0h, T1 = adj@Xth (+ e1h user half)
    k_spmm2<<<row_blocks, TPB>>>(rp_adj, cv_adj, e0h, Xth, S2, T1, e1h);
    // 9: T2 = adj@e1h fused with modal combine
    k_spmmT2_combine<<<row_blocks, TPB>>>(rp_adj, cv_adj, e1h,
                                          u_emb, XimgI, S1, S2, S3, T1, modal_w,
                                          modal, total, mh);
    // 10-12: GNN layer 1
    k_spmm<<<row_blocks, TPB>>>(rp_adj, cv_adj, mh, Ebuf, att_w + 0, scores);
    k_reduce<<<1, 1024>>>(scores, red);
    k_apply<<<ew_blocks, TPB>>>(Ebuf, scores, red, ch, total);
    // 13-15: GNN layer 2 + fused final
    k_spmm<<<row_blocks, TPB>>>(rp_adj, cv_adj, ch, Ebuf, att_w + DD, scores);
    k_reduce<<<1, 1024>>>(scores, red);
    k_apply2_final<<<row_blocks, TPB>>>(Ebuf, scores, red, total, modal, (float*)d_out);
}

// round 5
// speedup vs baseline: 1.6526x; 1.2725x over previous
#include <cuda_runtime.h>
#include <cuda_fp16.h>
#include <math.h>
#include <stdint.h>

// ---------------- problem constants ----------------
#define NN    100000
#define UU    50000
#define DD    64
#define EMAX  3200000
#define LEAK  0.2f
#define RIS_ADJ_LAMBDA 0.2f
#define RIS_LAMBDA     0.5f

#define CHUNK 2048
#define NB    ((NN + CHUNK - 1) / CHUNK)
#define NPART 64

// ---------------- static scratch ----------------
__device__ __half g_e0h  [(size_t)NN*DD];
__device__ __half g_e1h  [(size_t)NN*DD];
__device__ __half g_Xth  [(size_t)NN*DD];
__device__ __half g_mh   [(size_t)NN*DD];
__device__ __half g_ch   [(size_t)NN*DD];
__device__ float g_XimgI[(size_t)UU*DD];
__device__ float g_S1   [(size_t)NN*DD];
__device__ float g_S2   [(size_t)NN*DD];
__device__ float g_S3   [(size_t)NN*DD];
__device__ float g_T1   [(size_t)NN*DD];
__device__ float g_modal[(size_t)NN*DD];
__device__ float g_total[(size_t)NN*DD];
__device__ float g_E    [(size_t)NN*DD];
__device__ float g_scores[NN];
__device__ float g_redpart[2*NPART];
__device__ int   g_counts[3*NN];
__device__ int   g_rowptr[3*(NN+1)];
__device__ int   g_woff  [3*NN];
__device__ int   g_bsums [3*NB];
__device__ int2  g_colval[(size_t)3*EMAX];

// ---------------- helpers ----------------
__device__ __forceinline__ uint32_t smem_u32(const void* p) {
    return (uint32_t)__cvta_generic_to_shared(p);
}
__device__ __forceinline__ void ldm_x4(uint32_t& r0, uint32_t& r1,
                                       uint32_t& r2, uint32_t& r3, uint32_t a) {
    asm volatile("ldmatrix.sync.aligned.m8n8.x4.shared.b16 {%0,%1,%2,%3}, [%4];"
                 : "=r"(r0), "=r"(r1), "=r"(r2), "=r"(r3) : "r"(a));
}
__device__ __forceinline__ void ldm_x2t(uint32_t& r0, uint32_t& r1, uint32_t a) {
    asm volatile("ldmatrix.sync.aligned.m8n8.x2.trans.shared.b16 {%0,%1}, [%2];"
                 : "=r"(r0), "=r"(r1) : "r"(a));
}
__device__ __forceinline__ void mma16816(float* c, const uint32_t* a, const uint32_t* b) {
    asm volatile("mma.sync.aligned.m16n8k16.row.col.f32.f16.f16.f32 "
                 "{%0,%1,%2,%3}, {%4,%5,%6,%7}, {%8,%9}, {%0,%1,%2,%3};"
                 : "+f"(c[0]), "+f"(c[1]), "+f"(c[2]), "+f"(c[3])
                 : "r"(a[0]), "r"(a[1]), "r"(a[2]), "r"(a[3]), "r"(b[0]), "r"(b[1]));
}
// online softmax merge
__device__ __forceinline__ void msmerge(float& m, float& s, float m2, float s2) {
    float M = fmaxf(m, m2);
    s = s * expf(m - M) + s2 * expf(m2 - M);
    m = M;
}

// ---------------- launch 1: count + fp16 concat ----------------
__global__ void k_count3_concat(const int* __restrict__ r0, const int* __restrict__ r1,
                                const int* __restrict__ r2, int* __restrict__ cnt,
                                int e0, int e1, int e2,
                                const float* __restrict__ u, const float* __restrict__ it,
                                __half* __restrict__ e0h, __half* __restrict__ e1h,
                                __half* __restrict__ Xth) {
    int i = blockIdx.x * blockDim.x + threadIdx.x;
    if (i < e0) atomicAdd(&cnt[0 * NN + r0[i]], 1);
    if (i < e1) atomicAdd(&cnt[1 * NN + r1[i]], 1);
    if (i < e2) atomicAdd(&cnt[2 * NN + r2[i]], 1);
    size_t idx2 = (size_t)i;
    if (idx2 < (size_t)NN * DD / 2) {
        size_t idx = idx2 * 2;
        int n = (int)(idx >> 6);
        if (n < UU) {
            __half2 h = __float22half2_rn(*(const float2*)(u + idx));
            *(__half2*)(e0h + idx) = h;
            *(__half2*)(Xth + idx) = h;
        } else {
            __half2 h = __float22half2_rn(*(const float2*)(it + idx - (size_t)UU * DD));
            *(__half2*)(e0h + idx) = h;
            *(__half2*)(e1h + idx) = h;
        }
    }
}

// ---------------- scans ----------------
__global__ void k_scan1(const int* __restrict__ counts, int* __restrict__ bsums) {
    const int m = blockIdx.x / NB, b = blockIdx.x % NB;
    const int* c = counts + (size_t)m * NN;
    const int tid = threadIdx.x, lane = tid & 31, wid = tid >> 5;
    int base = b * CHUNK + tid * 8;
    int s = 0;
    #pragma unroll
    for (int k = 0; k < 8; k++) {
        int idx = base + k;
        if (idx < NN) s += c[idx];
    }
    #pragma unroll
    for (int o = 16; o; o >>= 1) s += __shfl_xor_sync(0xffffffffu, s, o);
    __shared__ int ws[8];
    if (lane == 0) ws[wid] = s;
    __syncthreads();
    if (tid == 0) {
        int t = 0;
        #pragma unroll
        for (int w = 0; w < 8; w++) t += ws[w];
        bsums[m * NB + b] = t;
    }
}

__global__ void k_scan3f(int* __restrict__ counts, const int* __restrict__ bsums,
                         int* __restrict__ rowptr, int* __restrict__ woff) {
    const int m = blockIdx.x / NB, b = blockIdx.x % NB;
    int* c = counts + (size_t)m * NN;
    int* rp = rowptr + (size_t)m * (NN + 1);
    int* wo = woff + (size_t)m * NN;
    const int tid = threadIdx.x, lane = tid & 31, wid = tid >> 5;

    __shared__ int sb[NB];
    if (tid < NB) sb[tid] = bsums[m * NB + tid];
    __syncthreads();
    int blockoff = 0;
    for (int i = 0; i < b; i++) blockoff += sb[i];
    if (b == 0 && tid == 0) {
        int tot = 0;
        for (int i = 0; i < NB; i++) tot += sb[i];
        rp[NN] = tot;
    }

    int base = b * CHUNK + tid * 8;
    int v[8], pre[8];
    int s = 0;
    #pragma unroll
    for (int k = 0; k < 8; k++) {
        int idx = base + k;
        v[k] = (idx < NN) ? c[idx] : 0;
        if (idx < NN) c[idx] = 0;
        s += v[k];
        pre[k] = s;
    }
    int tsum = s;
    int inc = tsum;
    #pragma unroll
    for (int o = 1; o < 32; o <<= 1) {
        int t = __shfl_up_sync(0xffffffffu, inc, o);
        if (lane >= o) inc += t;
    }
    __shared__ int ws[8];
    if (lane == 31) ws[wid] = inc;
    __syncthreads();
    int woffsum = 0;
    #pragma unroll
    for (int w = 0; w < 8; w++) woffsum += (w < wid) ? ws[w] : 0;
    int excl = blockoff + woffsum + inc - tsum;
    #pragma unroll
    for (int k = 0; k < 8; k++) {
        int idx = base + k;
        if (idx < NN) {
            int e = excl + pre[k] - v[k];
            rp[idx] = e;
            wo[idx] = e;
        }
    }
}

// ---------------- scatter ----------------
__global__ void k_scatter3(const int* __restrict__ ar, const int* __restrict__ ac,
                           const float* __restrict__ av,
                           const int* __restrict__ ir, const int* __restrict__ ic,
                           const float* __restrict__ iv,
                           const int* __restrict__ tr, const int* __restrict__ tc,
                           const float* __restrict__ tv,
                           int* __restrict__ woff, int2* __restrict__ colval,
                           int e0, int e1, int e2) {
    int i = blockIdx.x * blockDim.x + threadIdx.x;
    if (i < e0) {
        int p = atomicAdd(&woff[0 * NN + ar[i]], 1);
        colval[(size_t)0 * EMAX + p] = make_int2(ac[i], __float_as_int(av[i]));
    }
    if (i < e1) {
        int p = atomicAdd(&woff[1 * NN + ir[i]], 1);
        colval[(size_t)1 * EMAX + p] = make_int2(ic[i], __float_as_int(iv[i]));
    }
    if (i < e2) {
        int p = atomicAdd(&woff[2 * NN + tr[i]], 1);
        colval[(size_t)2 * EMAX + p] = make_int2(tc[i], __float_as_int(tv[i]));
    }
}

// ---------------- SpMM core ----------------
__device__ __forceinline__ void spmm_row(const int2* __restrict__ colval,
                                         const __half* __restrict__ x,
                                         int s, int e, int lane, float2& acc) {
    int base = s;
    for (; base + 32 <= e; base += 32) {
        int2 cv = colval[base + lane];
        #pragma unroll
        for (int j = 0; j < 32; j++) {
            int   c = __shfl_sync(0xffffffffu, cv.x, j);
            float v = __int_as_float(__shfl_sync(0xffffffffu, cv.y, j));
            float2 xv = __half22float2(*(const __half2*)(x + (size_t)c * DD + lane * 2));
            acc.x = fmaf(v, xv.x, acc.x);
            acc.y = fmaf(v, xv.y, acc.y);
        }
    }
    int rem = e - base;
    if (rem > 0) {
        int2 cv = (lane < rem) ? colval[base + lane] : make_int2(0, 0);
        for (int j = 0; j < rem; j++) {
            int   c = __shfl_sync(0xffffffffu, cv.x, j);
            float v = __int_as_float(__shfl_sync(0xffffffffu, cv.y, j));
            float2 xv = __half22float2(*(const __half2*)(x + (size_t)c * DD + lane * 2));
            acc.x = fmaf(v, xv.x, acc.x);
            acc.y = fmaf(v, xv.y, acc.y);
        }
    }
}

// all 4 modality spmms in ONE launch:
// gr in [0,NN):   S1 = img @ e0h
// gr in [NN,2NN): S3 = txt @ e0h
// gr in [2NN,3NN): S2 = adj @ e0h, T1 = adj @ Xth (shared user-half gather)
__global__ void k_spmm_modal(const int* __restrict__ rp_img, const int2* __restrict__ cv_img,
                             const int* __restrict__ rp_txt, const int2* __restrict__ cv_txt,
                             const int* __restrict__ rp_adj, const int2* __restrict__ cv_adj,
                             const __half* __restrict__ e0h, const __half* __restrict__ Xth,
                             float* __restrict__ S1, float* __restrict__ S3,
                             float* __restrict__ S2, float* __restrict__ T1,
                             __half* __restrict__ e1h) {
    int gr = (blockIdx.x * blockDim.x + threadIdx.x) >> 5;
    const int lane = threadIdx.x & 31;
    if (gr < NN) {
        float2 acc = make_float2(0.f, 0.f);
        spmm_row(cv_img, e0h, rp_img[gr], rp_img[gr + 1], lane, acc);
        *(float2*)(S1 + (size_t)gr * DD + lane * 2) = acc;
    } else if (gr < 2 * NN) {
        int row = gr - NN;
        float2 acc = make_float2(0.f, 0.f);
        spmm_row(cv_txt, e0h, rp_txt[row], rp_txt[row + 1], lane, acc);
        *(float2*)(S3 + (size_t)row * DD + lane * 2) = acc;
    } else if (gr < 3 * NN) {
        int row = gr - 2 * NN;
        const int s = rp_adj[row], e = rp_adj[row + 1];
        float2 a1 = make_float2(0.f, 0.f), a2 = make_float2(0.f, 0.f);
        int base = s;
        for (; base + 32 <= e; base += 32) {
            int2 cv = cv_adj[base + lane];
            #pragma unroll
            for (int j = 0; j < 32; j++) {
                int   c = __shfl_sync(0xffffffffu, cv.x, j);
                float v = __int_as_float(__shfl_sync(0xffffffffu, cv.y, j));
                size_t off = (size_t)c * DD + lane * 2;
                float2 p = __half22float2(*(const __half2*)(e0h + off));
                float2 q = (c < UU) ? p
                         : __half22float2(*(const __half2*)(Xth + off));
                a1.x = fmaf(v, p.x, a1.x); a1.y = fmaf(v, p.y, a1.y);
                a2.x = fmaf(v, q.x, a2.x); a2.y = fmaf(v, q.y, a2.y);
            }
        }
        int rem = e - base;
        if (rem > 0) {
            int2 cv = (lane < rem) ? cv_adj[base + lane] : make_int2(0, 0);
            for (int j = 0; j < rem; j++) {
                int   c = __shfl_sync(0xffffffffu, cv.x, j);
                float v = __int_as_float(__shfl_sync(0xffffffffu, cv.y, j));
                size_t off = (size_t)c * DD + lane * 2;
                float2 p = __half22float2(*(const __half2*)(e0h + off));
                float2 q = (c < UU) ? p
                         : __half22float2(*(const __half2*)(Xth + off));
                a1.x = fmaf(v, p.x, a1.x); a1.y = fmaf(v, p.y, a1.y);
                a2.x = fmaf(v, q.x, a2.x); a2.y = fmaf(v, q.y, a2.y);
            }
        }
        size_t off = (size_t)row * DD + lane * 2;
        *(float2*)(S2 + off) = a1;
        *(float2*)(T1 + off) = a2;
        if (row < UU) *(__half2*)(e1h + off) = __float22half2_rn(a2);
    }
}

// generic single spmm with attention-score epilogue
__global__ void k_spmm(const int* __restrict__ rowptr, const int2* __restrict__ colval,
                       const __half* __restrict__ x, float* __restrict__ y,
                       const float* __restrict__ attw, float* __restrict__ scores) {
    int row = (blockIdx.x * blockDim.x + threadIdx.x) >> 5;
    if (row >= NN) return;
    const int lane = threadIdx.x & 31;
    float2 acc = make_float2(0.f, 0.f);
    spmm_row(colval, x, rowptr[row], rowptr[row + 1], lane, acc);
    *(float2*)(y + (size_t)row * DD + lane * 2) = acc;
    float sc = acc.x * attw[lane * 2] + acc.y * attw[lane * 2 + 1];
    #pragma unroll
    for (int o = 16; o; o >>= 1) sc += __shfl_xor_sync(0xffffffffu, sc, o);
    if (lane == 0) scores[row] = sc;
}

// T2 = adj@e1h fused with modal combine
__global__ void k_spmmT2_combine(const int* __restrict__ rowptr,
                                 const int2* __restrict__ colval,
                                 const __half* __restrict__ x,
                                 const float* __restrict__ u,
                                 const float* __restrict__ XimgI,
                                 const float* __restrict__ S1,
                                 const float* __restrict__ S2,
                                 const float* __restrict__ S3,
                                 const float* __restrict__ T1,
                                 const float* __restrict__ mw,
                                 float* __restrict__ modal, float* __restrict__ total,
                                 __half* __restrict__ modalh) {
    int row = (blockIdx.x * blockDim.x + threadIdx.x) >> 5;
    if (row >= NN) return;
    const int lane = threadIdx.x & 31;
    float2 t2 = make_float2(0.f, 0.f);
    spmm_row(colval, x, rowptr[row], rowptr[row + 1], lane, t2);

    float a = mw[0], b = mw[1];
    float mx = fmaxf(a, b);
    float ea = expf(a - mx), eb = expf(b - mx);
    float w0 = ea / (ea + eb), w1 = eb / (ea + eb);

    size_t off = (size_t)row * DD + lane * 2;
    float2 s1 = *(const float2*)(S1 + off);
    float2 s2 = *(const float2*)(S2 + off);
    float2 s3 = *(const float2*)(S3 + off);
    float2 t1 = *(const float2*)(T1 + off);
    float2 xi = (row < UU) ? *(const float2*)(u + off)
                           : *(const float2*)(XimgI + off - (size_t)UU * DD);
    float eix = xi.x + s2.x + RIS_ADJ_LAMBDA * s1.x;
    float eiy = xi.y + s2.y + RIS_ADJ_LAMBDA * s1.y;
    float etx = t1.x + t2.x + RIS_ADJ_LAMBDA * s3.x;
    float ety = t1.y + t2.y + RIS_ADJ_LAMBDA * s3.y;
    float2 m = make_float2(w0 * eix + w1 * etx, w0 * eiy + w1 * ety);
    *(float2*)(modal + off) = m;
    *(float2*)(total + off) = m;
    *(__half2*)(modalh + off) = __float22half2_rn(m);
}

// ---------------- HMMA GEMM (M x K @ K x 64 + bias) + row l2norm ------------
// 256 threads, BM=128, BN=64, BK=32. Warp grid 4x2, warp tile 32x32.
__global__ void k_gemm_hmma(const float* __restrict__ A, const float* __restrict__ W,
                            const float* __restrict__ bias,
                            float* __restrict__ dstf, __half* __restrict__ dsth,
                            int M, int K) {
    __shared__ __half As[128 * 40];   // stride 40 halves (80B)
    __shared__ __half Ws[32 * 72];    // stride 72 halves (144B)
    __shared__ float  Cs[128 * 66];   // stride 66 floats
    const int tid = threadIdx.x;
    const int wid = tid >> 5, lane = tid & 31;
    const int wm = wid >> 1, wn = wid & 1;
    const int rowBase = blockIdx.x * 128;

    float acc[2][4][4];
    #pragma unroll
    for (int i = 0; i < 2; i++)
        #pragma unroll
        for (int j = 0; j < 4; j++)
            #pragma unroll
            for (int k = 0; k < 4; k++) acc[i][j][k] = 0.f;

    const int ra = tid >> 1, ha = tid & 1;          // A load: 2 thr/row
    const int rw = tid >> 3, sw = tid & 7;          // W load: 8 thr/row
    const bool avalid = (rowBase + ra) < M;

    for (int kc = 0; kc < K; kc += 32) {
        const float* ap = A + (size_t)(rowBase + ra) * K + kc + ha * 16;
        #pragma unroll
        for (int q = 0; q < 4; q++) {
            float4 f = avalid ? *(const float4*)(ap + q * 4)
                              : make_float4(0.f, 0.f, 0.f, 0.f);
            __half2* d = (__half2*)&As[ra * 40 + ha * 16 + q * 4];
            d[0] = __floats2half2_rn(f.x, f.y);
            d[1] = __floats2half2_rn(f.z, f.w);
        }
        const float* wp = W + (size_t)(kc + rw) * DD + sw * 8;
        #pragma unroll
        for (int q = 0; q < 2; q++) {
            float4 f = *(const float4*)(wp + q * 4);
            __half2* d = (__half2*)&Ws[rw * 72 + sw * 8 + q * 4];
            d[0] = __floats2half2_rn(f.x, f.y);
            d[1] = __floats2half2_rn(f.z, f.w);
        }
        __syncthreads();
        #pragma unroll
        for (int ks = 0; ks < 2; ks++) {
            uint32_t afr[2][4];
            #pragma unroll
            for (int mm = 0; mm < 2; mm++) {
                int mrow = wm * 32 + mm * 16 + (lane & 15);
                int kcol = ks * 16 + ((lane >> 4) << 3);
                ldm_x4(afr[mm][0], afr[mm][1], afr[mm][2], afr[mm][3],
                       smem_u32(&As[mrow * 40 + kcol]));
            }
            uint32_t bfr[4][2];
            #pragma unroll
            for (int nn = 0; nn < 4; nn++) {
                int krow = ks * 16 + (lane & 15);
                int ncol = wn * 32 + nn * 8;
                ldm_x2t(bfr[nn][0], bfr[nn][1], smem_u32(&Ws[krow * 72 + ncol]));
            }
            #pragma unroll
            for (int mm = 0; mm < 2; mm++)
                #pragma unroll
                for (int nn = 0; nn < 4; nn++)
                    mma16816(acc[mm][nn], afr[mm], bfr[nn]);
        }
        __syncthreads();
    }

    // stage C to smem
    #pragma unroll
    for (int mm = 0; mm < 2; mm++) {
        int r0 = wm * 32 + mm * 16 + (lane >> 2);
        #pragma unroll
        for (int nn = 0; nn < 4; nn++) {
            int c0 = wn * 32 + nn * 8 + (lane & 3) * 2;
            *(float2*)&Cs[r0 * 66 + c0]       = make_float2(acc[mm][nn][0], acc[mm][nn][1]);
            *(float2*)&Cs[(r0 + 8) * 66 + c0] = make_float2(acc[mm][nn][2], acc[mm][nn][3]);
        }
    }
    __syncthreads();

    // bias + row l2norm + store: warp w handles rows w*16 .. w*16+15
    float2 bv = *(const float2*)&bias[lane * 2];
    #pragma unroll
    for (int i = 0; i < 16; i++) {
        int r = wid * 16 + i;
        int g = rowBase + r;
        if (g >= M) break;
        float2 v = *(const float2*)&Cs[r * 66 + lane * 2];
        v.x += bv.x; v.y += bv.y;
        float ss = v.x * v.x + v.y * v.y;
        #pragma unroll
        for (int o = 16; o; o >>= 1) ss += __shfl_xor_sync(0xffffffffu, ss, o);
        float inv = 1.f / fmaxf(sqrtf(ss), 1e-12f);
        size_t off = (size_t)g * DD + lane * 2;
        if (dstf) *(float2*)&dstf[off] = make_float2(v.x * inv, v.y * inv);
        if (dsth) *(__half2*)&dsth[off] =
            __float22half2_rn(make_float2(v.x * inv, v.y * inv));
    }
}

// ---------------- softmax partials ----------------
__global__ void k_redpart(const float* __restrict__ scores, float* __restrict__ part) {
    const int tid = threadIdx.x, lane = tid & 31, wid = tid >> 5;
    float m = -3.4e38f, s = 0.f;
    for (int i = blockIdx.x * blockDim.x + tid; i < NN; i += gridDim.x * blockDim.x) {
        float x = scores[i];
        float M = fmaxf(m, x);
        s = s * expf(m - M) + expf(x - M);
        m = M;
    }
    #pragma unroll
    for (int o = 16; o; o >>= 1) {
        float m2 = __shfl_xor_sync(0xffffffffu, m, o);
        float s2 = __shfl_xor_sync(0xffffffffu, s, o);
        msmerge(m, s, m2, s2);
    }
    __shared__ float sm[8], ssum[8];
    if (lane == 0) { sm[wid] = m; ssum[wid] = s; }
    __syncthreads();
    if (tid == 0) {
        float M = sm[0], S = ssum[0];
        #pragma unroll
        for (int w = 1; w < 8; w++) msmerge(M, S, sm[w], ssum[w]);
        part[blockIdx.x * 2]     = M;
        part[blockIdx.x * 2 + 1] = S;
    }
}

// merge NPART partials (first warp), broadcast via smem
__device__ __forceinline__ void merge_partials(const float* __restrict__ part,
                                               float& M, float& S,
                                               float* sMS, int tid) {
    if (tid < 32) {
        float m = -3.4e38f, s = 0.f;
        #pragma unroll
        for (int i = tid; i < NPART; i += 32)
            msmerge(m, s, part[i * 2], part[i * 2 + 1]);
        #pragma unroll
        for (int o = 16; o; o >>= 1) {
            float m2 = __shfl_xor_sync(0xffffffffu, m, o);
            float s2 = __shfl_xor_sync(0xffffffffu, s, o);
            msmerge(m, s, m2, s2);
        }
        if (tid == 0) { sMS[0] = m; sMS[1] = s; }
    }
    __syncthreads();
    M = sMS[0]; S = sMS[1];
}

// layer-1 apply
__global__ void k_apply(const float* __restrict__ e, const float* __restrict__ scores,
                        const float* __restrict__ part, __half* __restrict__ curh,
                        float* __restrict__ total) {
    __shared__ float sMS[2];
    float M, S;
    merge_partials(part, M, S, sMS, threadIdx.x);
    size_t idx = (size_t)blockIdx.x * blockDim.x + threadIdx.x;
    if (idx >= (size_t)NN * DD) return;
    int n = (int)(idx >> 6);
    float att = expf(scores[n] - M) / S;
    float v = e[idx] * att;
    v = (v > 0.f) ? v : LEAK * v;
    curh[idx] = __float2half(v);
    total[idx] += v;
}

// layer-2 apply fused with final l2norm output (warp per row)
__global__ void k_apply2_final(const float* __restrict__ e, const float* __restrict__ scores,
                               const float* __restrict__ part,
                               const float* __restrict__ total,
                               const float* __restrict__ modal,
                               float* __restrict__ out) {
    __shared__ float sMS[2];
    float M, S;
    merge_partials(part, M, S, sMS, threadIdx.x);
    int row = (blockIdx.x * blockDim.x + threadIdx.x) >> 5;
    if (row >= NN) return;
    const int lane = threadIdx.x & 31;
    size_t off = (size_t)row * DD + lane * 2;
    float att = expf(scores[row] - M) / S;
    float2 ev = *(const float2*)(e + off);
    float vx = ev.x * att; vx = (vx > 0.f) ? vx : LEAK * vx;
    float vy = ev.y * att; vy = (vy > 0.f) ? vy : LEAK * vy;
    float2 t = *(const float2*)(total + off);
    t.x += vx; t.y += vy;
    float2 m = *(const float2*)(modal + off);
    float ss = m.x * m.x + m.y * m.y;
    #pragma unroll
    for (int o = 16; o; o >>= 1) ss += __shfl_xor_sync(0xffffffffu, ss, o);
    float inv = 1.f / fmaxf(sqrtf(ss), 1e-12f);
    *(float2*)(out + off) = make_float2(t.x + RIS_LAMBDA * m.x * inv,
                                        t.y + RIS_LAMBDA * m.y * inv);
}

// ---------------- host ----------------
extern "C" void kernel_launch(void* const* d_in, const int* in_sizes, int n_in,
                              void* d_out, int out_size) {
    const int*   adj_rows = (const int*)d_in[0];
    const int*   adj_cols = (const int*)d_in[1];
    const float* adj_vals = (const float*)d_in[2];
    const int*   img_rows = (const int*)d_in[3];
    const int*   img_cols = (const int*)d_in[4];
    const float* img_vals = (const float*)d_in[5];
    const int*   txt_rows = (const int*)d_in[6];
    const int*   txt_cols = (const int*)d_in[7];
    const float* txt_vals = (const float*)d_in[8];
    const float* u_emb    = (const float*)d_in[9];
    const float* i_emb    = (const float*)d_in[10];
    const float* img_W    = (const float*)d_in[11];
    const float* img_b    = (const float*)d_in[12];
    const float* txt_W    = (const float*)d_in[13];
    const float* txt_b    = (const float*)d_in[14];
    const float* modal_w  = (const float*)d_in[15];
    const float* att_w    = (const float*)d_in[16];
    const float* image_embedding = (const float*)d_in[17];
    const float* text_embedding  = (const float*)d_in[18];

    const int Eadj = in_sizes[0], Eimg = in_sizes[3], Etxt = in_sizes[6];
    int Emx = Eadj > Eimg ? Eadj : Eimg;
    if (Etxt > Emx) Emx = Etxt;
    long long fuse_n = (long long)NN * DD / 2;
    if ((long long)Emx > fuse_n) fuse_n = Emx;

    __half *e0h, *e1h, *Xth, *mh, *ch;
    float *XimgI, *S1, *S2, *S3, *T1, *modal, *total, *Ebuf;
    float *scores, *part;
    int *counts, *rowptr, *woff, *bsums;
    int2 *colval;
    cudaGetSymbolAddress((void**)&e0h,   g_e0h);
    cudaGetSymbolAddress((void**)&e1h,   g_e1h);
    cudaGetSymbolAddress((void**)&Xth,   g_Xth);
    cudaGetSymbolAddress((void**)&mh,    g_mh);
    cudaGetSymbolAddress((void**)&ch,    g_ch);
    cudaGetSymbolAddress((void**)&XimgI, g_XimgI);
    cudaGetSymbolAddress((void**)&S1,    g_S1);
    cudaGetSymbolAddress((void**)&S2,    g_S2);
    cudaGetSymbolAddress((void**)&S3,    g_S3);
    cudaGetSymbolAddress((void**)&T1,    g_T1);
    cudaGetSymbolAddress((void**)&modal, g_modal);
    cudaGetSymbolAddress((void**)&total, g_total);
    cudaGetSymbolAddress((void**)&Ebuf,  g_E);
    cudaGetSymbolAddress((void**)&scores,g_scores);
    cudaGetSymbolAddress((void**)&part,  g_redpart);
    cudaGetSymbolAddress((void**)&counts,g_counts);
    cudaGetSymbolAddress((void**)&rowptr,g_rowptr);
    cudaGetSymbolAddress((void**)&woff,  g_woff);
    cudaGetSymbolAddress((void**)&bsums, g_bsums);
    cudaGetSymbolAddress((void**)&colval,g_colval);

    const int TPB = 256;
    const int ew_blocks   = (NN * DD + TPB - 1) / TPB;
    const int row_blocks  = (NN * 32 + TPB - 1) / TPB;     // 12500
    const int fuse_blocks = (int)((fuse_n + TPB - 1) / TPB);

    const int* rp_adj = rowptr + 0 * (NN + 1);
    const int* rp_img = rowptr + 1 * (NN + 1);
    const int* rp_txt = rowptr + 2 * (NN + 1);
    const int2* cv_adj = colval + (size_t)0 * EMAX;
    const int2* cv_img = colval + (size_t)1 * EMAX;
    const int2* cv_txt = colval + (size_t)2 * EMAX;

    // 1: count + fp16 concat
    k_count3_concat<<<fuse_blocks, TPB>>>(adj_rows, img_rows, txt_rows, counts,
                                          Eadj, Eimg, Etxt,
                                          u_emb, i_emb, e0h, e1h, Xth);
    // 2-3: tensor-core projections + l2norm
    k_gemm_hmma<<<(UU + 127) / 128, 256>>>(image_embedding, img_W, img_b,
                                           XimgI, (half*)nullptr, UU, 1024);
    k_gemm_hmma<<<(UU + 127) / 128, 256>>>(text_embedding, txt_W, txt_b,
                                           (float*)nullptr, Xth + (size_t)UU * DD,
                                           UU, 384);
    // 4-5: scan
    k_scan1<<<3 * NB, 256>>>(counts, bsums);
    k_scan3f<<<3 * NB, 256>>>(counts, bsums, rowptr, woff);
    // 6: scatter
    k_scatter3<<<(Emx + TPB - 1) / TPB, TPB>>>(adj_rows, adj_cols, adj_vals,
                                               img_rows, img_cols, img_vals,
                                               txt_rows, txt_cols, txt_vals,
                                               woff, colval, Eadj, Eimg, Etxt);
    // 7: all four modality spmms (S1, S3, S2, T1 + e1h user half)
    k_spmm_modal<<<3 * row_blocks, TPB>>>(rp_img, cv_img, rp_txt, cv_txt,
                                          rp_adj, cv_adj, e0h, Xth,
                                          S1, S3, S2, T1, e1h);
    // 8: T2 + modal combine
    k_spmmT2_combine<<<row_blocks, TPB>>>(rp_adj, cv_adj, e1h,
                                          u_emb, XimgI, S1, S2, S3, T1, modal_w,
                                          modal, total, mh);
    // 9-11: GNN layer 1
    k_spmm<<<row_blocks, TPB>>>(rp_adj, cv_adj, mh, Ebuf, att_w + 0, scores);
    k_redpart<<<NPART, 256>>>(scores, part);
    k_apply<<<ew_blocks, TPB>>>(Ebuf, scores, part, ch, total);
    // 12-14: GNN layer 2 + fused final
    k_spmm<<<row_blocks, TPB>>>(rp_adj, cv_adj, ch, Ebuf, att_w + DD, scores);
    k_redpart<<<NPART, 256>>>(scores, part);
    k_apply2_final<<<row_blocks, TPB>>>(Ebuf, scores, part, total, modal, (float*)d_out);
}